// round 10
// baseline (speedup 1.0000x reference)
#include <cuda_runtime.h>
#include <math.h>
#include <cstdint>

#define Bn    16384
#define KINd  1024
#define MINd  64
#define Sd    256
#define Td    128
#define H1d   128
#define H2d   64

typedef unsigned long long ull;

// ------------------------- scratch (device globals; no allocs) --------------
static __device__ __align__(16) float g_Pw[6 * Sd * Sd];   // A^2,4,8,16,32,64
static __device__ __align__(16) float g_S[Sd * 128];       // Krylov cols A^n c
static __device__ __align__(16) float g_BT[Sd * MINd];     // B^T
static __device__ __align__(16) float g_M[Td * MINd];
static __device__ __align__(16) float g_h1[(size_t)Bn * 2 * H1d];   // 16 MB
static __device__ __align__(16) float g_h2[(size_t)Bn * 2 * H2d];   // 8 MB
static __device__ __align__(16) float g_inner[(size_t)Bn * 2];
static __device__ float g_sWb[2 * H2d];
static __device__ float g_sbb[2];
static __device__ volatile int g_sync[16];

// ---- FMA-only softplus (no MUFU) -------------------------------------------
__device__ __forceinline__ float sp_poly(float s) {
    float t = fmaxf(-fabsf(s), -17.f);
    float z = t * 1.44269504f;
    int   ni = __float2int_rn(z);
    float f = z - (float)ni;
    float p = 1.33335581e-3f;
    p = fmaf(p, f, 9.61812911e-3f);
    p = fmaf(p, f, 5.55041087e-2f);
    p = fmaf(p, f, 2.40226507e-1f);
    p = fmaf(p, f, 6.93147181e-1f);
    p = fmaf(p, f, 1.f);
    float y = __int_as_float((ni + 127) << 23) * p;
    float v = 2.f + y;
    float r0 = fmaf(-0.1716f, v, 0.8249f);
    r0 = r0 * fmaf(-v, r0, 2.f);
    r0 = r0 * fmaf(-v, r0, 2.f);
    float r  = y * r0;
    float r2 = r * r;
    float q = fmaf(r2, 0.28571429f, 0.4f);
    q = fmaf(r2, q, 0.66666667f);
    q = fmaf(r2, q, 2.f);
    return fmaxf(s, 0.f) + r * q;
}

// ---- packed f32x2 helpers ---------------------------------------------------
__device__ __forceinline__ void ffma2(ull& d, ull a, ull b) {
    asm("fma.rn.f32x2 %0, %1, %2, %0;" : "+l"(d) : "l"(a), "l"(b));
}
__device__ __forceinline__ void add2(ull& d, ull o) {
    asm("add.rn.f32x2 %0, %0, %1;" : "+l"(d) : "l"(o));
}
__device__ __forceinline__ ull pack2(float lo, float hi) {
    ull r; asm("mov.b64 %0, {%1, %2};" : "=l"(r) : "f"(lo), "f"(hi)); return r;
}
__device__ __forceinline__ void unpack2(ull v, float& lo, float& hi) {
    asm("mov.b64 {%0, %1}, %2;" : "=f"(lo), "=f"(hi) : "l"(v));
}

// ---- resident-grid sync (counters reset by ksums each replay) ---------------
__device__ __forceinline__ void grid_sync(int s, int n) {
    __threadfence();
    __syncthreads();
    if (threadIdx.x == 0) {
        atomicAdd((int*)&g_sync[s], 1);
        while (*(volatile int*)&g_sync[s] < n) { }
        __threadfence();
    }
    __syncthreads();
}

// ------------------------- A^(2^s), s=1..6, one kernel -----------------------
__global__ void __launch_bounds__(256) apow_kernel(const float* __restrict__ A) {
    extern __shared__ char dynsm[];
    float* As = (float*)dynsm;
    float* Bs = (float*)dynsm + 256 * 34;
    const int t = threadIdx.x, tx = t & 15, ty = t >> 4;
    const int rb = (blockIdx.x >> 3) * 32, cb = (blockIdx.x & 7) * 32;

#pragma unroll
    for (int s = 0; s < 6; ++s) {
        const float* L = (s == 0) ? A : g_Pw + (size_t)(s - 1) * Sd * Sd;
        float* C = g_Pw + (size_t)s * Sd * Sd;
        for (int q = t; q < 2048; q += 256) {
            int i = q >> 6, k4 = (q & 63) * 4;
            float4 v = *(const float4*)(L + (size_t)(rb + i) * Sd + k4);
            As[(k4 + 0) * 34 + i] = v.x;
            As[(k4 + 1) * 34 + i] = v.y;
            As[(k4 + 2) * 34 + i] = v.z;
            As[(k4 + 3) * 34 + i] = v.w;
        }
        for (int q = t; q < 2048; q += 256) {
            int k = q >> 3, j4 = (q & 7) * 4;
            *(float4*)&Bs[k * 36 + j4] = *(const float4*)(L + (size_t)k * Sd + cb + j4);
        }
        __syncthreads();
        float c00 = 0.f, c01 = 0.f, c10 = 0.f, c11 = 0.f;
#pragma unroll 8
        for (int k = 0; k < 256; ++k) {
            float2 av = *(float2*)&As[k * 34 + ty * 2];
            float2 bv = *(float2*)&Bs[k * 36 + tx * 2];
            c00 += av.x * bv.x; c01 += av.x * bv.y;
            c10 += av.y * bv.x; c11 += av.y * bv.y;
        }
        C[(size_t)(rb + ty * 2) * Sd + cb + tx * 2]         = c00;
        C[(size_t)(rb + ty * 2) * Sd + cb + tx * 2 + 1]     = c01;
        C[(size_t)(rb + ty * 2 + 1) * Sd + cb + tx * 2]     = c10;
        C[(size_t)(rb + ty * 2 + 1) * Sd + cb + tx * 2 + 1] = c11;
        if (s < 5) {
            grid_sync(s, 64);
            __syncthreads();
        }
    }
}

// ---- Vandermonde doubling: S=[c, Ac, ..., A^127 c], then M = B@S(reversed) --
__global__ void __launch_bounds__(256) vand_kernel(const float* __restrict__ A,
                                                   const float* __restrict__ Bssm,
                                                   const float* __restrict__ Cssm) {
    const int t = threadIdx.x;
    const int gtid = blockIdx.x * 256 + t;
    const int nth = 8 * 256;

    for (int idx = gtid; idx < MINd * Sd; idx += nth) {
        int m = idx >> 8, j = idx & 255;
        g_BT[j * MINd + m] = Bssm[idx];
    }
    for (int idx = gtid; idx < Sd; idx += nth) g_S[idx * 128] = Cssm[idx];
    grid_sync(5, 8);

    int width = 1;
#pragma unroll
    for (int k = 0; k < 7; ++k) {
        const float* Pk = (k == 0) ? A : g_Pw + (size_t)(k - 1) * Sd * Sd;
        const int nout = Sd * width;
        for (int idx = gtid; idx < nout; idx += nth) {
            const int i = idx >> k;
            const int cc = idx & (width - 1);
            const float* prow = Pk + (size_t)i * Sd;
            float a0 = 0.f, a1 = 0.f, a2 = 0.f, a3 = 0.f;
#pragma unroll 4
            for (int j = 0; j < 256; j += 4) {
                a0 += prow[j + 0] * __ldcg(g_S + (j + 0) * 128 + cc);
                a1 += prow[j + 1] * __ldcg(g_S + (j + 1) * 128 + cc);
                a2 += prow[j + 2] * __ldcg(g_S + (j + 2) * 128 + cc);
                a3 += prow[j + 3] * __ldcg(g_S + (j + 3) * 128 + cc);
            }
            g_S[(size_t)i * 128 + width + cc] = (a0 + a1) + (a2 + a3);
        }
        grid_sync(6 + k, 8);
        width <<= 1;
    }

    for (int idx = gtid; idx < Td * MINd; idx += nth) {
        const int tau = idx >> 6, m = idx & 63;
        const int col = 127 - tau;
        float a0 = 0.f, a1 = 0.f;
#pragma unroll 4
        for (int j = 0; j < 256; j += 2) {
            a0 += g_BT[(j + 0) * MINd + m] * __ldcg(g_S + (j + 0) * 128 + col);
            a1 += g_BT[(j + 1) * MINd + m] * __ldcg(g_S + (j + 1) * 128 + col);
        }
        g_M[idx] = a0 + a1;
    }
}

// row-sums of in_wb / in_bb (bias-collapse) + sync-counter reset for replays
__global__ void ksums_kernel(const float* __restrict__ wb,
                             const float* __restrict__ bb) {
    int r = blockIdx.x, lane = threadIdx.x;
    if (r == 0 && lane == 0) {
#pragma unroll
        for (int s = 0; s < 16; ++s) g_sync[s] = 0;
    }
    float s = 0.f;
    if (r < 128) {
        const float* row = wb + (size_t)r * KINd;
        for (int i = lane; i < KINd; i += 32) s += row[i];
    } else if (r < 130) {
        const float* row = bb + (size_t)(r - 128) * KINd;
        for (int i = lane; i < KINd; i += 32) s += row[i];
    }
#pragma unroll
    for (int o = 16; o > 0; o >>= 1) s += __shfl_down_sync(0xffffffffu, s, o);
    if (lane == 0) {
        if (r < 128) g_sWb[r] = s;
        else if (r < 130) g_sbb[r - 128] = s;
    }
}

// ---------- combined kernel: gemm1 (blocks 0..255) + mamba reduce (256..) ----
__global__ void __launch_bounds__(256) g1mamba_kernel(const float* __restrict__ x,
                                                      const float* __restrict__ w1,
                                                      const float* __restrict__ b1,
                                                      const float* __restrict__ xm,
                                                      const float* __restrict__ wm,
                                                      float* __restrict__ out) {
    extern __shared__ char dynsm[];
    const int vb = blockIdx.x;
    const int t = threadIdx.x;

    if (vb < 256) {
        // ---- gemm1 path: f32x2 SIMT, 128x128 tile ----
        float* xs = (float*)dynsm;               // [128][36]
        float* ws = (float*)dynsm + 128 * 36;    // [32][128]
        const int u = vb & 1;
        const int b0 = (vb >> 1) * 128;
        const int tx = t & 15;
        const int ty = t >> 4;
        const float* w1u = w1 + (size_t)u * KINd * H1d;
        const float* b1u = b1 + (size_t)u * H1d;

        ull acc2[8][4];
#pragma unroll
        for (int r = 0; r < 8; ++r)
#pragma unroll
            for (int j = 0; j < 4; ++j) acc2[r][j] = 0ULL;

        for (int k0 = 0; k0 < KINd; k0 += 32) {
            for (int q = t; q < 1024; q += 256) {
                int r = q >> 3, c = q & 7;
                *(float4*)&xs[r * 36 + c * 4] =
                    *(const float4*)(x + (size_t)(b0 + r) * KINd + k0 + c * 4);
            }
            for (int q = t; q < 1024; q += 256) {
                int r = q >> 5, c = q & 31;
                *(float4*)&ws[r * 128 + c * 4] =
                    *(const float4*)(w1u + (size_t)(k0 + r) * H1d + c * 4);
            }
            __syncthreads();
#pragma unroll 4
            for (int kk = 0; kk < 32; ++kk) {
                ull ap[8];
#pragma unroll
                for (int r = 0; r < 8; ++r) {
                    float a = xs[(ty * 8 + r) * 36 + kk];
                    ap[r] = pack2(a, a);
                }
                ulonglong2 wa = *(const ulonglong2*)&ws[kk * 128 + tx * 8];
                ulonglong2 wb = *(const ulonglong2*)&ws[kk * 128 + tx * 8 + 4];
#pragma unroll
                for (int r = 0; r < 8; ++r) {
                    ffma2(acc2[r][0], ap[r], wa.x);
                    ffma2(acc2[r][1], ap[r], wa.y);
                    ffma2(acc2[r][2], ap[r], wb.x);
                    ffma2(acc2[r][3], ap[r], wb.y);
                }
            }
            __syncthreads();
        }
#pragma unroll
        for (int r = 0; r < 8; ++r) {
            int b = b0 + ty * 8 + r;
            float* dst = g_h1 + ((size_t)b * 2 + u) * H1d + tx * 8;
#pragma unroll
            for (int j = 0; j < 4; ++j) {
                float lo, hi;
                unpack2(acc2[r][j], lo, hi);
                int n = tx * 8 + 2 * j;
                float v0 = fmaxf(lo + b1u[n], 0.f);
                float v1 = fmaxf(hi + b1u[n + 1], 0.f);
                float2 o2; o2.x = v0; o2.y = v1;
                *(float2*)(dst + 2 * j) = o2;
            }
        }
    } else {
        // ---- mamba path: 8 warps, one row each ----
        float4* Ms = (float4*)dynsm;     // 2048 float4 = 32 KB
        const float4* Mg = (const float4*)g_M;
        for (int q = t; q < 2048; q += 256) Ms[q] = Mg[q];
        __syncthreads();
        const int warp = t >> 5, lane = t & 31;
        const int b = (vb - 256) * 8 + warp;
        const float4* xr = (const float4*)(xm + (size_t)b * (Td * MINd));
        float acc = 0.f;
#pragma unroll 8
        for (int j = lane; j < 2048; j += 32) {
            float4 xv = xr[j];
            float4 mv = Ms[j];
            acc += xv.x * mv.x + xv.y * mv.y + xv.z * mv.z + xv.w * mv.w;
        }
#pragma unroll
        for (int o = 16; o > 0; o >>= 1) acc += __shfl_down_sync(0xffffffffu, acc, o);
        if (lane == 0) out[b] = wm[0] * acc;
    }
}

// h2 = relu(h1 @ W2[u] + b2[u])
__global__ void __launch_bounds__(256) gemm2_kernel(const float* __restrict__ w2,
                                                    const float* __restrict__ b2) {
    __shared__ float hs[64][65];
    __shared__ float w2s[64][64];
    const int u = blockIdx.x;
    const int b0 = blockIdx.y * 64;
    const int t = threadIdx.x;
    const int tx = t & 15;
    const int ty = t >> 4;
    const float* w2u = w2 + (size_t)u * H1d * H2d;

    float acc[4][4];
#pragma unroll
    for (int i = 0; i < 4; ++i)
#pragma unroll
        for (int j = 0; j < 4; ++j) acc[i][j] = 0.f;

    for (int k0 = 0; k0 < H1d; k0 += 64) {
        for (int q = t; q < 1024; q += 256) {
            int r = q >> 4, c = q & 15;
            float4 v = *(const float4*)(g_h1 + ((size_t)(b0 + r) * 2 + u) * H1d + k0 + c * 4);
            hs[r][c * 4 + 0] = v.x; hs[r][c * 4 + 1] = v.y;
            hs[r][c * 4 + 2] = v.z; hs[r][c * 4 + 3] = v.w;
        }
        for (int q = t; q < 1024; q += 256) {
            int r = q >> 4, c = q & 15;
            *(float4*)&w2s[r][c * 4] = *(const float4*)(w2u + (size_t)(k0 + r) * H2d + c * 4);
        }
        __syncthreads();
#pragma unroll 8
        for (int f = 0; f < 64; ++f) {
            float4 w = *(float4*)&w2s[f][tx * 4];
            float a0 = hs[ty * 4 + 0][f];
            float a1 = hs[ty * 4 + 1][f];
            float a2 = hs[ty * 4 + 2][f];
            float a3 = hs[ty * 4 + 3][f];
            acc[0][0] += a0 * w.x; acc[0][1] += a0 * w.y; acc[0][2] += a0 * w.z; acc[0][3] += a0 * w.w;
            acc[1][0] += a1 * w.x; acc[1][1] += a1 * w.y; acc[1][2] += a1 * w.z; acc[1][3] += a1 * w.w;
            acc[2][0] += a2 * w.x; acc[2][1] += a2 * w.y; acc[2][2] += a2 * w.z; acc[2][3] += a2 * w.w;
            acc[3][0] += a3 * w.x; acc[3][1] += a3 * w.y; acc[3][2] += a3 * w.z; acc[3][3] += a3 * w.w;
        }
        __syncthreads();
    }
#pragma unroll
    for (int i = 0; i < 4; ++i) {
        int b = b0 + ty * 4 + i;
#pragma unroll
        for (int j = 0; j < 4; ++j) {
            int g = tx * 4 + j;
            float v = acc[i][j] + b2[u * H2d + g];
            g_h2[((size_t)b * 2 + u) * H2d + g] = fmaxf(v, 0.f);
        }
    }
}

// inner[b,u] = sum_i softplus(h2.Ww[:,i]+bw[i])*x[b,i] + h2.sWb + sbb
__global__ void __launch_bounds__(256) stage2_kernel(const float* __restrict__ x,
                                                     const float* __restrict__ ww,
                                                     const float* __restrict__ bw) {
    extern __shared__ char dynsm[];
    float* h2tf = (float*)dynsm;           // [64][132]
    float* wws  = h2tf + 64 * 132;         // [64][68]
    float* xsh  = wws + 64 * 68;           // [128][68]
    float* bws  = xsh + 128 * 68;          // [64]
    float* sWbs = bws + 64;                // [64]
    const int u = blockIdx.x;
    const int b0 = blockIdx.y * 128;
    const int t = threadIdx.x;
    const int tx = t & 15;
    const int ty = t >> 4;
    const float* wwu = ww + (size_t)u * H2d * KINd;
    const float* bwu = bw + (size_t)u * KINd;

    if (t < 64) sWbs[t] = g_sWb[u * H2d + t];
    for (int q = t; q < 2048; q += 256) {
        int r = q & 127, gq = (q >> 7) * 4;
        float4 v = *(const float4*)(g_h2 + ((size_t)(b0 + r) * 2 + u) * H2d + gq);
        h2tf[(gq + 0) * 132 + r] = v.x;
        h2tf[(gq + 1) * 132 + r] = v.y;
        h2tf[(gq + 2) * 132 + r] = v.z;
        h2tf[(gq + 3) * 132 + r] = v.w;
    }
    __syncthreads();

    ull acc2[4][4];
    float part[8];
#pragma unroll
    for (int r = 0; r < 8; ++r) part[r] = 0.f;

    for (int it = 0; it < 16; ++it) {
        int i0 = it * 64;
        __syncthreads();
        for (int q = t; q < 1024; q += 256) {
            int r = q >> 4, c = q & 15;
            *(float4*)&wws[r * 68 + c * 4] =
                *(const float4*)(wwu + (size_t)r * KINd + i0 + c * 4);
        }
        for (int q = t; q < 2048; q += 256) {
            int r = q >> 4, c = q & 15;
            *(float4*)&xsh[r * 68 + c * 4] =
                *(const float4*)(x + (size_t)(b0 + r) * KINd + i0 + c * 4);
        }
        if (t < 16) *(float4*)&bws[t * 4] = *(const float4*)(bwu + i0 + t * 4);
        __syncthreads();

#pragma unroll
        for (int rp = 0; rp < 4; ++rp)
#pragma unroll
            for (int j = 0; j < 4; ++j) acc2[rp][j] = 0ULL;

#pragma unroll 4
        for (int g = 0; g < 64; ++g) {
            ulonglong2 ha = *(const ulonglong2*)(h2tf + g * 132 + ty * 8);
            ulonglong2 hb = *(const ulonglong2*)(h2tf + g * 132 + ty * 8 + 4);
            float4 wv = *(const float4*)&wws[g * 68 + tx * 4];
            ull w0 = pack2(wv.x, wv.x), w1p = pack2(wv.y, wv.y);
            ull w2p = pack2(wv.z, wv.z), w3p = pack2(wv.w, wv.w);
            ffma2(acc2[0][0], ha.x, w0); ffma2(acc2[0][1], ha.x, w1p);
            ffma2(acc2[0][2], ha.x, w2p); ffma2(acc2[0][3], ha.x, w3p);
            ffma2(acc2[1][0], ha.y, w0); ffma2(acc2[1][1], ha.y, w1p);
            ffma2(acc2[1][2], ha.y, w2p); ffma2(acc2[1][3], ha.y, w3p);
            ffma2(acc2[2][0], hb.x, w0); ffma2(acc2[2][1], hb.x, w1p);
            ffma2(acc2[2][2], hb.x, w2p); ffma2(acc2[2][3], hb.x, w3p);
            ffma2(acc2[3][0], hb.y, w0); ffma2(acc2[3][1], hb.y, w1p);
            ffma2(acc2[3][2], hb.y, w2p); ffma2(acc2[3][3], hb.y, w3p);
        }

#pragma unroll
        for (int j = 0; j < 4; ++j) {
            float bwv = bws[tx * 4 + j];
#pragma unroll
            for (int rp = 0; rp < 4; ++rp) {
                float s0, s1;
                unpack2(acc2[rp][j], s0, s1);
                float p0 = sp_poly(s0 + bwv);
                float p1 = sp_poly(s1 + bwv);
                part[2 * rp]     += p0 * xsh[(ty * 8 + 2 * rp) * 68 + tx * 4 + j];
                part[2 * rp + 1] += p1 * xsh[(ty * 8 + 2 * rp + 1) * 68 + tx * 4 + j];
            }
        }
    }

#pragma unroll
    for (int gg = 0; gg < 4; ++gg) {
        int g = tx * 4 + gg;
        float swv = sWbs[g];
#pragma unroll
        for (int r = 0; r < 8; ++r)
            part[r] += h2tf[g * 132 + ty * 8 + r] * swv;
    }
#pragma unroll
    for (int r = 0; r < 8; ++r)
#pragma unroll
        for (int o = 8; o > 0; o >>= 1)
            part[r] += __shfl_down_sync(0xffffffffu, part[r], o, 16);
    if (tx == 0) {
        float sbbv = g_sbb[u];
#pragma unroll
        for (int r = 0; r < 8; ++r)
            g_inner[(size_t)(b0 + ty * 8 + r) * 2 + u] = part[r] + sbbv;
    }
}

// outer MLP: out[b] += wk * kan_out[b]; thread = (b, v, f-half)
__global__ void __launch_bounds__(512) outer_kernel(const float* __restrict__ ow1,
                                                    const float* __restrict__ ob1,
                                                    const float* __restrict__ ow2,
                                                    const float* __restrict__ ob2,
                                                    const float* __restrict__ oww,
                                                    const float* __restrict__ obw,
                                                    const float* __restrict__ owb,
                                                    const float* __restrict__ obb,
                                                    const float* __restrict__ wk,
                                                    float* __restrict__ out) {
    extern __shared__ char dynsm[];
    float* OW2f = (float*)dynsm;   // [2][128][68]
    __shared__ float w1as[2][128], w1bs[2][128], b1s[2][128];
    __shared__ float ob2s[2][64], owws[2][64], owbs[2][64];
    const int t = threadIdx.x;
    const int bl = t >> 2;
    const int v = (t >> 1) & 1;
    const int hf = t & 1;
    const int b = blockIdx.x * 128 + bl;

    for (int q = t; q < 4096; q += 512) {
        int vv = q >> 11, f = (q >> 4) & 127, c = q & 15;
        *(float4*)&OW2f[(vv * 128 + f) * 68 + c * 4] =
            *(const float4*)(ow2 + ((size_t)vv * 128 + f) * 64 + c * 4);
    }
    if (t < 256) {
        int vv = t >> 7, f = t & 127;
        w1as[vv][f] = ow1[(vv * 2 + 0) * 128 + f];
        w1bs[vv][f] = ow1[(vv * 2 + 1) * 128 + f];
        b1s[vv][f]  = ob1[vv * 128 + f];
    }
    if (t < 128) {
        int vv = t >> 6, j = t & 63;
        ob2s[vv][j] = ob2[vv * 64 + j];
        owws[vv][j] = oww[vv * 64 + j];
        owbs[vv][j] = owb[vv * 64 + j];
    }
    __syncthreads();

    const float i0 = g_inner[(size_t)b * 2 + 0];
    const float i1 = g_inner[(size_t)b * 2 + 1];

    ull g2a[32];
#pragma unroll
    for (int j = 0; j < 32; ++j)
        g2a[j] = (hf == 0) ? pack2(ob2s[v][2 * j], ob2s[v][2 * j + 1]) : 0ULL;

    const float* OW2v = OW2f + v * 128 * 68;
#pragma unroll 2
    for (int ff = 0; ff < 64; ++ff) {
        int f = hf * 64 + ff;
        float g1f = fmaxf(fmaf(i0, w1as[v][f], fmaf(i1, w1bs[v][f], b1s[v][f])), 0.f);
        ull g1p = pack2(g1f, g1f);
        const ull* row = (const ull*)(OW2v + f * 68);
#pragma unroll
        for (int j = 0; j < 32; ++j) ffma2(g2a[j], g1p, row[j]);
    }
#pragma unroll
    for (int j = 0; j < 32; ++j) {
        ull o = __shfl_xor_sync(0xffffffffu, g2a[j], 1);
        add2(g2a[j], o);
    }
    float sw = 0.f, sb = 0.f;
#pragma unroll
    for (int j = 0; j < 32; ++j) {
        float a, c2;
        unpack2(g2a[j], a, c2);
        a = fmaxf(a, 0.f); c2 = fmaxf(c2, 0.f);
        sw += a * owws[v][2 * j] + c2 * owws[v][2 * j + 1];
        sb += a * owbs[v][2 * j] + c2 * owbs[v][2 * j + 1];
    }
    float wout = sp_poly(sw + obw[v]);
    float bout = sb + obb[v];
    float term = wout * (i0 + i1) + 2.f * bout;
    term += __shfl_xor_sync(0xffffffffu, term, 2);
    if ((t & 3) == 0) out[b] += wk[0] * term;
}

extern "C" void kernel_launch(void* const* d_in, const int* in_sizes, int n_in,
                              void* d_out, int out_size) {
    const float* x_kan   = (const float*)d_in[0];
    const float* x_mamba = (const float*)d_in[1];
    const float* in_w1 = (const float*)d_in[2];
    const float* in_b1 = (const float*)d_in[3];
    const float* in_w2 = (const float*)d_in[4];
    const float* in_b2 = (const float*)d_in[5];
    const float* in_ww = (const float*)d_in[6];
    const float* in_bw = (const float*)d_in[7];
    const float* in_wb = (const float*)d_in[8];
    const float* in_bb = (const float*)d_in[9];
    const float* out_w1 = (const float*)d_in[10];
    const float* out_b1 = (const float*)d_in[11];
    const float* out_w2 = (const float*)d_in[12];
    const float* out_b2 = (const float*)d_in[13];
    const float* out_ww = (const float*)d_in[14];
    const float* out_bw = (const float*)d_in[15];
    const float* out_wb = (const float*)d_in[16];
    const float* out_bb = (const float*)d_in[17];
    const float* A      = (const float*)d_in[18];
    const float* B_ssm  = (const float*)d_in[19];
    const float* C_ssm  = (const float*)d_in[20];
    const float* wk     = (const float*)d_in[21];
    const float* wm     = (const float*)d_in[22];
    float* out = (float*)d_out;

    const int APSMEM = (256 * 34 + 256 * 36) * 4;                        // 71680
    const int G1SMEM = (128 * 36 + 32 * 128) * 4;                        // 34816
    const int S2SMEM = (64 * 132 + 64 * 68 + 128 * 68 + 64 + 64) * 4;    // 86528
    const int OSMEM  = 2 * 128 * 68 * 4;                                  // 69632
    cudaFuncSetAttribute(apow_kernel, cudaFuncAttributeMaxDynamicSharedMemorySize, APSMEM);
    cudaFuncSetAttribute(stage2_kernel, cudaFuncAttributeMaxDynamicSharedMemorySize, S2SMEM);
    cudaFuncSetAttribute(outer_kernel, cudaFuncAttributeMaxDynamicSharedMemorySize, OSMEM);

    ksums_kernel<<<130, 32>>>(in_wb, in_bb);                          // 1 (+ctr reset)
    apow_kernel<<<64, 256, APSMEM>>>(A);                              // 2 (A^2..A^64)
    vand_kernel<<<8, 256>>>(A, B_ssm, C_ssm);                         // 3 (g_M)
    g1mamba_kernel<<<2304, 256, G1SMEM>>>(x_kan, in_w1, in_b1,
                                          x_mamba, wm, out);          // 4 (profiled slot)
    gemm2_kernel<<<dim3(2, Bn / 64), 256>>>(in_w2, in_b2);            // 5
    stage2_kernel<<<dim3(2, Bn / 128), 256, S2SMEM>>>(x_kan, in_ww, in_bw); // 6
    outer_kernel<<<Bn / 128, 512, OSMEM>>>(out_w1, out_b1, out_w2, out_b2,
                                           out_ww, out_bw, out_wb, out_bb, wk, out); // 7
}

// round 11
// speedup vs baseline: 1.3889x; 1.3889x over previous
#include <cuda_runtime.h>
#include <math.h>
#include <cstdint>

#define Bn    16384
#define KINd  1024
#define MINd  64
#define Sd    256
#define Td    128
#define H1d   128
#define H2d   64

typedef unsigned long long ull;

// ------------------------- scratch (device globals; no allocs) --------------
static __device__ __align__(16) float g_Pw[6 * Sd * Sd];   // A^2,4,8,16,32,64
static __device__ __align__(16) float g_ST[128 * Sd];      // S^T: row n = A^n c
static __device__ __align__(16) float g_M[Td * MINd];
static __device__ __align__(16) float g_h1[(size_t)Bn * 2 * H1d];   // 16 MB
static __device__ __align__(16) float g_h2[(size_t)Bn * 2 * H2d];   // 8 MB
static __device__ __align__(16) float g_inner[(size_t)Bn * 2];
static __device__ float g_sWb[2 * H2d];
static __device__ float g_sbb[2];
static __device__ volatile int g_sync[16];   // [15] = M-ready counter

// ---- FMA-only softplus (no MUFU) -------------------------------------------
__device__ __forceinline__ float sp_poly(float s) {
    float t = fmaxf(-fabsf(s), -17.f);
    float z = t * 1.44269504f;
    int   ni = __float2int_rn(z);
    float f = z - (float)ni;
    float p = 1.33335581e-3f;
    p = fmaf(p, f, 9.61812911e-3f);
    p = fmaf(p, f, 5.55041087e-2f);
    p = fmaf(p, f, 2.40226507e-1f);
    p = fmaf(p, f, 6.93147181e-1f);
    p = fmaf(p, f, 1.f);
    float y = __int_as_float((ni + 127) << 23) * p;
    float v = 2.f + y;
    float r0 = fmaf(-0.1716f, v, 0.8249f);
    r0 = r0 * fmaf(-v, r0, 2.f);
    r0 = r0 * fmaf(-v, r0, 2.f);
    float r  = y * r0;
    float r2 = r * r;
    float q = fmaf(r2, 0.28571429f, 0.4f);
    q = fmaf(r2, q, 0.66666667f);
    q = fmaf(r2, q, 2.f);
    return fmaxf(s, 0.f) + r * q;
}

// ---- packed f32x2 helpers ---------------------------------------------------
__device__ __forceinline__ void ffma2(ull& d, ull a, ull b) {
    asm("fma.rn.f32x2 %0, %1, %2, %0;" : "+l"(d) : "l"(a), "l"(b));
}
__device__ __forceinline__ void add2(ull& d, ull o) {
    asm("add.rn.f32x2 %0, %0, %1;" : "+l"(d) : "l"(o));
}
__device__ __forceinline__ ull pack2(float lo, float hi) {
    ull r; asm("mov.b64 %0, {%1, %2};" : "=l"(r) : "f"(lo), "f"(hi)); return r;
}
__device__ __forceinline__ void unpack2(ull v, float& lo, float& hi) {
    asm("mov.b64 {%0, %1}, %2;" : "=f"(lo), "=f"(hi) : "l"(v));
}

// ---- resident-grid sync among prelude blocks (counters reset by ksums) ------
__device__ __forceinline__ void grid_sync(int s, int n) {
    __threadfence();
    __syncthreads();
    if (threadIdx.x == 0) {
        atomicAdd((int*)&g_sync[s], 1);
        while (*(volatile int*)&g_sync[s] < n) { }
        __threadfence();
    }
    __syncthreads();
}

// row-sums of in_wb / in_bb (bias-collapse) + sync-counter reset for replays
__global__ void ksums_kernel(const float* __restrict__ wb,
                             const float* __restrict__ bb) {
    int r = blockIdx.x, lane = threadIdx.x;
    if (r == 0 && lane == 0) {
#pragma unroll
        for (int s = 0; s < 16; ++s) g_sync[s] = 0;
    }
    float s = 0.f;
    if (r < 128) {
        const float* row = wb + (size_t)r * KINd;
        for (int i = lane; i < KINd; i += 32) s += row[i];
    } else if (r < 130) {
        const float* row = bb + (size_t)(r - 128) * KINd;
        for (int i = lane; i < KINd; i += 32) s += row[i];
    }
#pragma unroll
    for (int o = 16; o > 0; o >>= 1) s += __shfl_down_sync(0xffffffffu, s, o);
    if (lane == 0) {
        if (r < 128) g_sWb[r] = s;
        else if (r < 130) g_sbb[r - 128] = s;
    }
}

// ---------- MEGA kernel ------------------------------------------------------
// blocks 0..63    : SSM prelude (A powers -> Krylov doubling -> M), grid-synced
// blocks 64..319  : gemm1  h1 = relu(x @ W1[u] + b1[u])  (f32x2 SIMT)
// blocks 320..2367: mamba  out[b] = wm * <x_mamba[b], M>  (waits on M-ready)
__global__ void __launch_bounds__(256) mega_kernel(const float* __restrict__ x,
                                                   const float* __restrict__ w1,
                                                   const float* __restrict__ b1,
                                                   const float* __restrict__ xm,
                                                   const float* __restrict__ wm,
                                                   const float* __restrict__ A,
                                                   const float* __restrict__ Bssm,
                                                   const float* __restrict__ Cssm,
                                                   float* __restrict__ out) {
    extern __shared__ char dynsm[];
    const int vb = blockIdx.x;
    const int t = threadIdx.x;

    if (vb < 64) {
        // ================= prelude =================
        float* As = (float*)dynsm;            // [256][34] transposed L tile
        float* Bs = (float*)dynsm + 256 * 34; // [256][36] R tile
        const int tx = t & 15, ty = t >> 4;
        const int rb = (vb >> 3) * 32, cb = (vb & 7) * 32;
        const int warp = t >> 5, lane = t & 31;
        const int wgid = vb * 8 + warp;       // 0..511

        if (vb == 0) g_ST[t] = Cssm[t];       // S^T row 0 = c

        // --- 6 squarings: A^2..A^64 ---
#pragma unroll
        for (int s = 0; s < 6; ++s) {
            const float* L = (s == 0) ? A : g_Pw + (size_t)(s - 1) * Sd * Sd;
            float* C = g_Pw + (size_t)s * Sd * Sd;
            for (int q = t; q < 2048; q += 256) {
                int i = q >> 6, k4 = (q & 63) * 4;
                float4 v = *(const float4*)(L + (size_t)(rb + i) * Sd + k4);
                As[(k4 + 0) * 34 + i] = v.x;
                As[(k4 + 1) * 34 + i] = v.y;
                As[(k4 + 2) * 34 + i] = v.z;
                As[(k4 + 3) * 34 + i] = v.w;
            }
            for (int q = t; q < 2048; q += 256) {
                int k = q >> 3, j4 = (q & 7) * 4;
                *(float4*)&Bs[k * 36 + j4] = *(const float4*)(L + (size_t)k * Sd + cb + j4);
            }
            __syncthreads();
            float c00 = 0.f, c01 = 0.f, c10 = 0.f, c11 = 0.f;
#pragma unroll 8
            for (int k = 0; k < 256; ++k) {
                float2 av = *(float2*)&As[k * 34 + ty * 2];
                float2 bv = *(float2*)&Bs[k * 36 + tx * 2];
                c00 += av.x * bv.x; c01 += av.x * bv.y;
                c10 += av.y * bv.x; c11 += av.y * bv.y;
            }
            C[(size_t)(rb + ty * 2) * Sd + cb + tx * 2]         = c00;
            C[(size_t)(rb + ty * 2) * Sd + cb + tx * 2 + 1]     = c01;
            C[(size_t)(rb + ty * 2 + 1) * Sd + cb + tx * 2]     = c10;
            C[(size_t)(rb + ty * 2 + 1) * Sd + cb + tx * 2 + 1] = c11;
            if (s < 5) grid_sync(s, 64);
        }

        // --- 7 Krylov doubling steps: S^T rows [width, 2*width) ---
        int width = 1;
#pragma unroll
        for (int k = 0; k < 7; ++k) {
            const float* Pb = (k == 0) ? A : g_Pw + (size_t)(k - 1) * Sd * Sd;
            const int nout = Sd * width;
            for (int e = wgid; e < nout; e += 512) {
                const int cc = e >> 8, i = e & 255;
                const float4* p4 = (const float4*)(Pb + (size_t)i * Sd);
                const float4* s4 = (const float4*)(g_ST + cc * Sd);
                float4 a0 = p4[2 * lane], a1 = p4[2 * lane + 1];
                float4 s0 = s4[2 * lane], s1 = s4[2 * lane + 1];
                float acc = a0.x * s0.x + a0.y * s0.y + a0.z * s0.z + a0.w * s0.w
                          + a1.x * s1.x + a1.y * s1.y + a1.z * s1.z + a1.w * s1.w;
#pragma unroll
                for (int o = 16; o > 0; o >>= 1)
                    acc += __shfl_down_sync(0xffffffffu, acc, o);
                if (lane == 0) g_ST[(width + cc) * Sd + i] = acc;
            }
            grid_sync(5 + k, 64);
            width <<= 1;
        }

        // --- M[tau][m] = B[m,:] . S^T[127-tau] ---
        for (int e = wgid; e < Td * MINd; e += 512) {
            const int tau = e >> 6, m = e & 63;
            const float4* b4 = (const float4*)(Bssm + (size_t)m * Sd);
            const float4* s4 = (const float4*)(g_ST + (127 - tau) * Sd);
            float4 a0 = b4[2 * lane], a1 = b4[2 * lane + 1];
            float4 s0 = s4[2 * lane], s1 = s4[2 * lane + 1];
            float acc = a0.x * s0.x + a0.y * s0.y + a0.z * s0.z + a0.w * s0.w
                      + a1.x * s1.x + a1.y * s1.y + a1.z * s1.z + a1.w * s1.w;
#pragma unroll
            for (int o = 16; o > 0; o >>= 1)
                acc += __shfl_down_sync(0xffffffffu, acc, o);
            if (lane == 0) g_M[tau * MINd + m] = acc;
        }
        __threadfence();
        __syncthreads();
        if (t == 0) atomicAdd((int*)&g_sync[15], 1);   // release M
    } else if (vb < 320) {
        // ================= gemm1 (f32x2 SIMT, 128x128 tile) =================
        float* xs = (float*)dynsm;               // [128][36]
        float* ws = (float*)dynsm + 128 * 36;    // [32][128]
        const int vg = vb - 64;
        const int u = vg & 1;
        const int b0 = (vg >> 1) * 128;
        const int tx = t & 15;
        const int ty = t >> 4;
        const float* w1u = w1 + (size_t)u * KINd * H1d;
        const float* b1u = b1 + (size_t)u * H1d;

        ull acc2[8][4];
#pragma unroll
        for (int r = 0; r < 8; ++r)
#pragma unroll
            for (int j = 0; j < 4; ++j) acc2[r][j] = 0ULL;

        for (int k0 = 0; k0 < KINd; k0 += 32) {
            for (int q = t; q < 1024; q += 256) {
                int r = q >> 3, c = q & 7;
                *(float4*)&xs[r * 36 + c * 4] =
                    *(const float4*)(x + (size_t)(b0 + r) * KINd + k0 + c * 4);
            }
            for (int q = t; q < 1024; q += 256) {
                int r = q >> 5, c = q & 31;
                *(float4*)&ws[r * 128 + c * 4] =
                    *(const float4*)(w1u + (size_t)(k0 + r) * H1d + c * 4);
            }
            __syncthreads();
#pragma unroll 4
            for (int kk = 0; kk < 32; ++kk) {
                ull ap[8];
#pragma unroll
                for (int r = 0; r < 8; ++r) {
                    float a = xs[(ty * 8 + r) * 36 + kk];
                    ap[r] = pack2(a, a);
                }
                ulonglong2 wa = *(const ulonglong2*)&ws[kk * 128 + tx * 8];
                ulonglong2 wb = *(const ulonglong2*)&ws[kk * 128 + tx * 8 + 4];
#pragma unroll
                for (int r = 0; r < 8; ++r) {
                    ffma2(acc2[r][0], ap[r], wa.x);
                    ffma2(acc2[r][1], ap[r], wa.y);
                    ffma2(acc2[r][2], ap[r], wb.x);
                    ffma2(acc2[r][3], ap[r], wb.y);
                }
            }
            __syncthreads();
        }
#pragma unroll
        for (int r = 0; r < 8; ++r) {
            int b = b0 + ty * 8 + r;
            float* dst = g_h1 + ((size_t)b * 2 + u) * H1d + tx * 8;
#pragma unroll
            for (int j = 0; j < 4; ++j) {
                float lo, hi;
                unpack2(acc2[r][j], lo, hi);
                int n = tx * 8 + 2 * j;
                float v0 = fmaxf(lo + b1u[n], 0.f);
                float v1 = fmaxf(hi + b1u[n + 1], 0.f);
                float2 o2; o2.x = v0; o2.y = v1;
                *(float2*)(dst + 2 * j) = o2;
            }
        }
    } else {
        // ================= mamba: 8 warps, one row each =================
        if (t == 0) {
            while (*(volatile int*)&g_sync[15] < 64) { }
            __threadfence();
        }
        __syncthreads();
        float4* Ms = (float4*)dynsm;     // 2048 float4 = 32 KB
        const float4* Mg = (const float4*)g_M;
        for (int q = t; q < 2048; q += 256) Ms[q] = __ldcg(Mg + q);
        __syncthreads();
        const int warp = t >> 5, lane = t & 31;
        const int b = (vb - 320) * 8 + warp;
        const float4* xr = (const float4*)(xm + (size_t)b * (Td * MINd));
        float acc = 0.f;
#pragma unroll 8
        for (int j = lane; j < 2048; j += 32) {
            float4 xv = xr[j];
            float4 mv = Ms[j];
            acc += xv.x * mv.x + xv.y * mv.y + xv.z * mv.z + xv.w * mv.w;
        }
#pragma unroll
        for (int o = 16; o > 0; o >>= 1) acc += __shfl_down_sync(0xffffffffu, acc, o);
        if (lane == 0) out[b] = wm[0] * acc;
    }
}

// h2 = relu(h1 @ W2[u] + b2[u])
__global__ void __launch_bounds__(256) gemm2_kernel(const float* __restrict__ w2,
                                                    const float* __restrict__ b2) {
    __shared__ float hs[64][65];
    __shared__ float w2s[64][64];
    const int u = blockIdx.x;
    const int b0 = blockIdx.y * 64;
    const int t = threadIdx.x;
    const int tx = t & 15;
    const int ty = t >> 4;
    const float* w2u = w2 + (size_t)u * H1d * H2d;

    float acc[4][4];
#pragma unroll
    for (int i = 0; i < 4; ++i)
#pragma unroll
        for (int j = 0; j < 4; ++j) acc[i][j] = 0.f;

    for (int k0 = 0; k0 < H1d; k0 += 64) {
        for (int q = t; q < 1024; q += 256) {
            int r = q >> 4, c = q & 15;
            float4 v = *(const float4*)(g_h1 + ((size_t)(b0 + r) * 2 + u) * H1d + k0 + c * 4);
            hs[r][c * 4 + 0] = v.x; hs[r][c * 4 + 1] = v.y;
            hs[r][c * 4 + 2] = v.z; hs[r][c * 4 + 3] = v.w;
        }
        for (int q = t; q < 1024; q += 256) {
            int r = q >> 4, c = q & 15;
            *(float4*)&w2s[r][c * 4] = *(const float4*)(w2u + (size_t)(k0 + r) * H2d + c * 4);
        }
        __syncthreads();
#pragma unroll 8
        for (int f = 0; f < 64; ++f) {
            float4 w = *(float4*)&w2s[f][tx * 4];
            float a0 = hs[ty * 4 + 0][f];
            float a1 = hs[ty * 4 + 1][f];
            float a2 = hs[ty * 4 + 2][f];
            float a3 = hs[ty * 4 + 3][f];
            acc[0][0] += a0 * w.x; acc[0][1] += a0 * w.y; acc[0][2] += a0 * w.z; acc[0][3] += a0 * w.w;
            acc[1][0] += a1 * w.x; acc[1][1] += a1 * w.y; acc[1][2] += a1 * w.z; acc[1][3] += a1 * w.w;
            acc[2][0] += a2 * w.x; acc[2][1] += a2 * w.y; acc[2][2] += a2 * w.z; acc[2][3] += a2 * w.w;
            acc[3][0] += a3 * w.x; acc[3][1] += a3 * w.y; acc[3][2] += a3 * w.z; acc[3][3] += a3 * w.w;
        }
        __syncthreads();
    }
#pragma unroll
    for (int i = 0; i < 4; ++i) {
        int b = b0 + ty * 4 + i;
#pragma unroll
        for (int j = 0; j < 4; ++j) {
            int g = tx * 4 + j;
            float v = acc[i][j] + b2[u * H2d + g];
            g_h2[((size_t)b * 2 + u) * H2d + g] = fmaxf(v, 0.f);
        }
    }
}

// inner[b,u] = sum_i softplus(h2.Ww[:,i]+bw[i])*x[b,i] + h2.sWb + sbb
__global__ void __launch_bounds__(256) stage2_kernel(const float* __restrict__ x,
                                                     const float* __restrict__ ww,
                                                     const float* __restrict__ bw) {
    extern __shared__ char dynsm[];
    float* h2tf = (float*)dynsm;           // [64][132]
    float* wws  = h2tf + 64 * 132;         // [64][68]
    float* xsh  = wws + 64 * 68;           // [128][68]
    float* bws  = xsh + 128 * 68;          // [64]
    float* sWbs = bws + 64;                // [64]
    const int u = blockIdx.x;
    const int b0 = blockIdx.y * 128;
    const int t = threadIdx.x;
    const int tx = t & 15;
    const int ty = t >> 4;
    const float* wwu = ww + (size_t)u * H2d * KINd;
    const float* bwu = bw + (size_t)u * KINd;

    if (t < 64) sWbs[t] = g_sWb[u * H2d + t];
    for (int q = t; q < 2048; q += 256) {
        int r = q & 127, gq = (q >> 7) * 4;
        float4 v = *(const float4*)(g_h2 + ((size_t)(b0 + r) * 2 + u) * H2d + gq);
        h2tf[(gq + 0) * 132 + r] = v.x;
        h2tf[(gq + 1) * 132 + r] = v.y;
        h2tf[(gq + 2) * 132 + r] = v.z;
        h2tf[(gq + 3) * 132 + r] = v.w;
    }
    __syncthreads();

    ull acc2[4][4];
    float part[8];
#pragma unroll
    for (int r = 0; r < 8; ++r) part[r] = 0.f;

    for (int it = 0; it < 16; ++it) {
        int i0 = it * 64;
        __syncthreads();
        for (int q = t; q < 1024; q += 256) {
            int r = q >> 4, c = q & 15;
            *(float4*)&wws[r * 68 + c * 4] =
                *(const float4*)(wwu + (size_t)r * KINd + i0 + c * 4);
        }
        for (int q = t; q < 2048; q += 256) {
            int r = q >> 4, c = q & 15;
            *(float4*)&xsh[r * 68 + c * 4] =
                *(const float4*)(x + (size_t)(b0 + r) * KINd + i0 + c * 4);
        }
        if (t < 16) *(float4*)&bws[t * 4] = *(const float4*)(bwu + i0 + t * 4);
        __syncthreads();

#pragma unroll
        for (int rp = 0; rp < 4; ++rp)
#pragma unroll
            for (int j = 0; j < 4; ++j) acc2[rp][j] = 0ULL;

#pragma unroll 4
        for (int g = 0; g < 64; ++g) {
            ulonglong2 ha = *(const ulonglong2*)(h2tf + g * 132 + ty * 8);
            ulonglong2 hb = *(const ulonglong2*)(h2tf + g * 132 + ty * 8 + 4);
            float4 wv = *(const float4*)&wws[g * 68 + tx * 4];
            ull w0 = pack2(wv.x, wv.x), w1p = pack2(wv.y, wv.y);
            ull w2p = pack2(wv.z, wv.z), w3p = pack2(wv.w, wv.w);
            ffma2(acc2[0][0], ha.x, w0); ffma2(acc2[0][1], ha.x, w1p);
            ffma2(acc2[0][2], ha.x, w2p); ffma2(acc2[0][3], ha.x, w3p);
            ffma2(acc2[1][0], ha.y, w0); ffma2(acc2[1][1], ha.y, w1p);
            ffma2(acc2[1][2], ha.y, w2p); ffma2(acc2[1][3], ha.y, w3p);
            ffma2(acc2[2][0], hb.x, w0); ffma2(acc2[2][1], hb.x, w1p);
            ffma2(acc2[2][2], hb.x, w2p); ffma2(acc2[2][3], hb.x, w3p);
            ffma2(acc2[3][0], hb.y, w0); ffma2(acc2[3][1], hb.y, w1p);
            ffma2(acc2[3][2], hb.y, w2p); ffma2(acc2[3][3], hb.y, w3p);
        }

#pragma unroll
        for (int j = 0; j < 4; ++j) {
            float bwv = bws[tx * 4 + j];
#pragma unroll
            for (int rp = 0; rp < 4; ++rp) {
                float s0, s1;
                unpack2(acc2[rp][j], s0, s1);
                float p0 = sp_poly(s0 + bwv);
                float p1 = sp_poly(s1 + bwv);
                part[2 * rp]     += p0 * xsh[(ty * 8 + 2 * rp) * 68 + tx * 4 + j];
                part[2 * rp + 1] += p1 * xsh[(ty * 8 + 2 * rp + 1) * 68 + tx * 4 + j];
            }
        }
    }

#pragma unroll
    for (int gg = 0; gg < 4; ++gg) {
        int g = tx * 4 + gg;
        float swv = sWbs[g];
#pragma unroll
        for (int r = 0; r < 8; ++r)
            part[r] += h2tf[g * 132 + ty * 8 + r] * swv;
    }
#pragma unroll
    for (int r = 0; r < 8; ++r)
#pragma unroll
        for (int o = 8; o > 0; o >>= 1)
            part[r] += __shfl_down_sync(0xffffffffu, part[r], o, 16);
    if (tx == 0) {
        float sbbv = g_sbb[u];
#pragma unroll
        for (int r = 0; r < 8; ++r)
            g_inner[(size_t)(b0 + ty * 8 + r) * 2 + u] = part[r] + sbbv;
    }
}

// outer MLP: out[b] += wk * kan_out[b]; thread = (b, v, f-half)
__global__ void __launch_bounds__(512) outer_kernel(const float* __restrict__ ow1,
                                                    const float* __restrict__ ob1,
                                                    const float* __restrict__ ow2,
                                                    const float* __restrict__ ob2,
                                                    const float* __restrict__ oww,
                                                    const float* __restrict__ obw,
                                                    const float* __restrict__ owb,
                                                    const float* __restrict__ obb,
                                                    const float* __restrict__ wk,
                                                    float* __restrict__ out) {
    extern __shared__ char dynsm[];
    float* OW2f = (float*)dynsm;   // [2][128][68]
    __shared__ float w1as[2][128], w1bs[2][128], b1s[2][128];
    __shared__ float ob2s[2][64], owws[2][64], owbs[2][64];
    const int t = threadIdx.x;
    const int bl = t >> 2;
    const int v = (t >> 1) & 1;
    const int hf = t & 1;
    const int b = blockIdx.x * 128 + bl;

    for (int q = t; q < 4096; q += 512) {
        int vv = q >> 11, f = (q >> 4) & 127, c = q & 15;
        *(float4*)&OW2f[(vv * 128 + f) * 68 + c * 4] =
            *(const float4*)(ow2 + ((size_t)vv * 128 + f) * 64 + c * 4);
    }
    if (t < 256) {
        int vv = t >> 7, f = t & 127;
        w1as[vv][f] = ow1[(vv * 2 + 0) * 128 + f];
        w1bs[vv][f] = ow1[(vv * 2 + 1) * 128 + f];
        b1s[vv][f]  = ob1[vv * 128 + f];
    }
    if (t < 128) {
        int vv = t >> 6, j = t & 63;
        ob2s[vv][j] = ob2[vv * 64 + j];
        owws[vv][j] = oww[vv * 64 + j];
        owbs[vv][j] = owb[vv * 64 + j];
    }
    __syncthreads();

    const float i0 = g_inner[(size_t)b * 2 + 0];
    const float i1 = g_inner[(size_t)b * 2 + 1];

    ull g2a[32];
#pragma unroll
    for (int j = 0; j < 32; ++j)
        g2a[j] = (hf == 0) ? pack2(ob2s[v][2 * j], ob2s[v][2 * j + 1]) : 0ULL;

    const float* OW2v = OW2f + v * 128 * 68;
#pragma unroll 2
    for (int ff = 0; ff < 64; ++ff) {
        int f = hf * 64 + ff;
        float g1f = fmaxf(fmaf(i0, w1as[v][f], fmaf(i1, w1bs[v][f], b1s[v][f])), 0.f);
        ull g1p = pack2(g1f, g1f);
        const ull* row = (const ull*)(OW2v + f * 68);
#pragma unroll
        for (int j = 0; j < 32; ++j) ffma2(g2a[j], g1p, row[j]);
    }
#pragma unroll
    for (int j = 0; j < 32; ++j) {
        ull o = __shfl_xor_sync(0xffffffffu, g2a[j], 1);
        add2(g2a[j], o);
    }
    float sw = 0.f, sb = 0.f;
#pragma unroll
    for (int j = 0; j < 32; ++j) {
        float a, c2;
        unpack2(g2a[j], a, c2);
        a = fmaxf(a, 0.f); c2 = fmaxf(c2, 0.f);
        sw += a * owws[v][2 * j] + c2 * owws[v][2 * j + 1];
        sb += a * owbs[v][2 * j] + c2 * owbs[v][2 * j + 1];
    }
    float wout = sp_poly(sw + obw[v]);
    float bout = sb + obb[v];
    float term = wout * (i0 + i1) + 2.f * bout;
    term += __shfl_xor_sync(0xffffffffu, term, 2);
    if ((t & 3) == 0) out[b] += wk[0] * term;
}

extern "C" void kernel_launch(void* const* d_in, const int* in_sizes, int n_in,
                              void* d_out, int out_size) {
    const float* x_kan   = (const float*)d_in[0];
    const float* x_mamba = (const float*)d_in[1];
    const float* in_w1 = (const float*)d_in[2];
    const float* in_b1 = (const float*)d_in[3];
    const float* in_w2 = (const float*)d_in[4];
    const float* in_b2 = (const float*)d_in[5];
    const float* in_ww = (const float*)d_in[6];
    const float* in_bw = (const float*)d_in[7];
    const float* in_wb = (const float*)d_in[8];
    const float* in_bb = (const float*)d_in[9];
    const float* out_w1 = (const float*)d_in[10];
    const float* out_b1 = (const float*)d_in[11];
    const float* out_w2 = (const float*)d_in[12];
    const float* out_b2 = (const float*)d_in[13];
    const float* out_ww = (const float*)d_in[14];
    const float* out_bw = (const float*)d_in[15];
    const float* out_wb = (const float*)d_in[16];
    const float* out_bb = (const float*)d_in[17];
    const float* A      = (const float*)d_in[18];
    const float* B_ssm  = (const float*)d_in[19];
    const float* C_ssm  = (const float*)d_in[20];
    const float* wk     = (const float*)d_in[21];
    const float* wm     = (const float*)d_in[22];
    float* out = (float*)d_out;

    const int MGSMEM = (256 * 34 + 256 * 36) * 4;                        // 71680 (max of 3 paths)
    const int S2SMEM = (64 * 132 + 64 * 68 + 128 * 68 + 64 + 64) * 4;    // 86528
    const int OSMEM  = 2 * 128 * 68 * 4;                                  // 69632
    cudaFuncSetAttribute(mega_kernel, cudaFuncAttributeMaxDynamicSharedMemorySize, MGSMEM);
    cudaFuncSetAttribute(stage2_kernel, cudaFuncAttributeMaxDynamicSharedMemorySize, S2SMEM);
    cudaFuncSetAttribute(outer_kernel, cudaFuncAttributeMaxDynamicSharedMemorySize, OSMEM);

    ksums_kernel<<<130, 32>>>(in_wb, in_bb);                          // 1 (+ctr reset)
    mega_kernel<<<64 + 256 + 2048, 256, MGSMEM>>>(x_kan, in_w1, in_b1,
                                                  x_mamba, wm,
                                                  A, B_ssm, C_ssm, out); // 2
    gemm2_kernel<<<dim3(2, Bn / 64), 256>>>(in_w2, in_b2);            // 3
    stage2_kernel<<<dim3(2, Bn / 128), 256, S2SMEM>>>(x_kan, in_ww, in_bw); // 4 (profiled)
    outer_kernel<<<Bn / 128, 512, OSMEM>>>(out_w1, out_b1, out_w2, out_b2,
                                           out_ww, out_bw, out_wb, out_bb, wk, out); // 5
}

// round 12
// speedup vs baseline: 1.4091x; 1.0145x over previous
#include <cuda_runtime.h>
#include <math.h>
#include <cstdint>

#define Bn    16384
#define KINd  1024
#define MINd  64
#define Sd    256
#define Td    128
#define H1d   128
#define H2d   64

typedef unsigned long long ull;

// ------------------------- scratch (device globals; no allocs) --------------
static __device__ __align__(16) float g_Pw[6 * Sd * Sd];   // A^2,4,8,16,32,64
static __device__ __align__(16) float g_ST[128 * Sd];      // S^T: row n = A^n c
static __device__ __align__(16) float g_M[Td * MINd];
static __device__ __align__(16) float g_h1[(size_t)Bn * 2 * H1d];   // 16 MB
static __device__ __align__(16) float g_h2[(size_t)Bn * 2 * H2d];   // 8 MB
static __device__ __align__(16) float g_inner[(size_t)Bn * 2];
static __device__ float g_sWb[2 * H2d];
static __device__ float g_sbb[2];
static __device__ volatile int g_sync[16];    // [15] = M-ready counter
static __device__ volatile int g_tdone[256];  // gemm1 tile-done flags

// ---- FMA-only softplus (no MUFU) -------------------------------------------
__device__ __forceinline__ float sp_poly(float s) {
    float t = fmaxf(-fabsf(s), -17.f);
    float z = t * 1.44269504f;
    int   ni = __float2int_rn(z);
    float f = z - (float)ni;
    float p = 1.33335581e-3f;
    p = fmaf(p, f, 9.61812911e-3f);
    p = fmaf(p, f, 5.55041087e-2f);
    p = fmaf(p, f, 2.40226507e-1f);
    p = fmaf(p, f, 6.93147181e-1f);
    p = fmaf(p, f, 1.f);
    float y = __int_as_float((ni + 127) << 23) * p;
    float v = 2.f + y;
    float r0 = fmaf(-0.1716f, v, 0.8249f);
    r0 = r0 * fmaf(-v, r0, 2.f);
    r0 = r0 * fmaf(-v, r0, 2.f);
    float r  = y * r0;
    float r2 = r * r;
    float q = fmaf(r2, 0.28571429f, 0.4f);
    q = fmaf(r2, q, 0.66666667f);
    q = fmaf(r2, q, 2.f);
    return fmaxf(s, 0.f) + r * q;
}

// ---- packed f32x2 helpers ---------------------------------------------------
__device__ __forceinline__ void ffma2(ull& d, ull a, ull b) {
    asm("fma.rn.f32x2 %0, %1, %2, %0;" : "+l"(d) : "l"(a), "l"(b));
}
__device__ __forceinline__ void add2(ull& d, ull o) {
    asm("add.rn.f32x2 %0, %0, %1;" : "+l"(d) : "l"(o));
}
__device__ __forceinline__ ull pack2(float lo, float hi) {
    ull r; asm("mov.b64 %0, {%1, %2};" : "=l"(r) : "f"(lo), "f"(hi)); return r;
}
__device__ __forceinline__ void unpack2(ull v, float& lo, float& hi) {
    asm("mov.b64 {%0, %1}, %2;" : "=f"(lo), "=f"(hi) : "l"(v));
}

// ---- resident-grid sync among prelude blocks (counters reset by ksums) ------
__device__ __forceinline__ void grid_sync(int s, int n) {
    __threadfence();
    __syncthreads();
    if (threadIdx.x == 0) {
        atomicAdd((int*)&g_sync[s], 1);
        while (*(volatile int*)&g_sync[s] < n) { }
        __threadfence();
    }
    __syncthreads();
}

// row-sums of in_wb / in_bb (bias-collapse) + counter/flag reset for replays
__global__ void ksums_kernel(const float* __restrict__ wb,
                             const float* __restrict__ bb) {
    int r = blockIdx.x, lane = threadIdx.x;
    if (r == 0) {
        if (lane == 0)
#pragma unroll
            for (int s = 0; s < 16; ++s) g_sync[s] = 0;
        for (int i = lane; i < 256; i += 32) g_tdone[i] = 0;
    }
    float s = 0.f;
    if (r < 128) {
        const float* row = wb + (size_t)r * KINd;
        for (int i = lane; i < KINd; i += 32) s += row[i];
    } else if (r < 130) {
        const float* row = bb + (size_t)(r - 128) * KINd;
        for (int i = lane; i < KINd; i += 32) s += row[i];
    }
#pragma unroll
    for (int o = 16; o > 0; o >>= 1) s += __shfl_down_sync(0xffffffffu, s, o);
    if (lane == 0) {
        if (r < 128) g_sWb[r] = s;
        else if (r < 130) g_sbb[r - 128] = s;
    }
}

// ---------- MEGA kernel ------------------------------------------------------
// blocks 0..63     : SSM prelude (A powers -> Krylov doubling -> M)
// blocks 64..319   : gemm1  h1 = relu(x @ W1[u] + b1[u])  (sets tile flags)
// blocks 320..2367 : mamba  out[b] = wm * <x_mamba[b], M> (waits on M-ready)
// blocks 2368..2879: gemm2  h2 = relu(h1 @ W2[u] + b2[u]) (waits on tile flag)
__global__ void __launch_bounds__(256) mega_kernel(const float* __restrict__ x,
                                                   const float* __restrict__ w1,
                                                   const float* __restrict__ b1,
                                                   const float* __restrict__ xm,
                                                   const float* __restrict__ wm,
                                                   const float* __restrict__ A,
                                                   const float* __restrict__ Bssm,
                                                   const float* __restrict__ Cssm,
                                                   const float* __restrict__ w2,
                                                   const float* __restrict__ b2,
                                                   float* __restrict__ out) {
    extern __shared__ char dynsm[];
    const int vb = blockIdx.x;
    const int t = threadIdx.x;

    if (vb < 64) {
        // ================= prelude =================
        float* As = (float*)dynsm;            // [256][34] transposed L tile
        float* Bs = (float*)dynsm + 256 * 34; // [256][36] R tile
        const int tx = t & 15, ty = t >> 4;
        const int rb = (vb >> 3) * 32, cb = (vb & 7) * 32;
        const int warp = t >> 5, lane = t & 31;
        const int wgid = vb * 8 + warp;       // 0..511

        if (vb == 0) g_ST[t] = Cssm[t];       // S^T row 0 = c

#pragma unroll
        for (int s = 0; s < 6; ++s) {
            const float* L = (s == 0) ? A : g_Pw + (size_t)(s - 1) * Sd * Sd;
            float* C = g_Pw + (size_t)s * Sd * Sd;
            for (int q = t; q < 2048; q += 256) {
                int i = q >> 6, k4 = (q & 63) * 4;
                float4 v = *(const float4*)(L + (size_t)(rb + i) * Sd + k4);
                As[(k4 + 0) * 34 + i] = v.x;
                As[(k4 + 1) * 34 + i] = v.y;
                As[(k4 + 2) * 34 + i] = v.z;
                As[(k4 + 3) * 34 + i] = v.w;
            }
            for (int q = t; q < 2048; q += 256) {
                int k = q >> 3, j4 = (q & 7) * 4;
                *(float4*)&Bs[k * 36 + j4] = *(const float4*)(L + (size_t)k * Sd + cb + j4);
            }
            __syncthreads();
            float c00 = 0.f, c01 = 0.f, c10 = 0.f, c11 = 0.f;
#pragma unroll 8
            for (int k = 0; k < 256; ++k) {
                float2 av = *(float2*)&As[k * 34 + ty * 2];
                float2 bv = *(float2*)&Bs[k * 36 + tx * 2];
                c00 += av.x * bv.x; c01 += av.x * bv.y;
                c10 += av.y * bv.x; c11 += av.y * bv.y;
            }
            C[(size_t)(rb + ty * 2) * Sd + cb + tx * 2]         = c00;
            C[(size_t)(rb + ty * 2) * Sd + cb + tx * 2 + 1]     = c01;
            C[(size_t)(rb + ty * 2 + 1) * Sd + cb + tx * 2]     = c10;
            C[(size_t)(rb + ty * 2 + 1) * Sd + cb + tx * 2 + 1] = c11;
            if (s < 5) grid_sync(s, 64);
        }

        int width = 1;
#pragma unroll
        for (int k = 0; k < 7; ++k) {
            const float* Pb = (k == 0) ? A : g_Pw + (size_t)(k - 1) * Sd * Sd;
            const int nout = Sd * width;
            for (int e = wgid; e < nout; e += 512) {
                const int cc = e >> 8, i = e & 255;
                const float4* p4 = (const float4*)(Pb + (size_t)i * Sd);
                const float4* s4 = (const float4*)(g_ST + cc * Sd);
                float4 a0 = p4[2 * lane], a1 = p4[2 * lane + 1];
                float4 s0 = s4[2 * lane], s1 = s4[2 * lane + 1];
                float acc = a0.x * s0.x + a0.y * s0.y + a0.z * s0.z + a0.w * s0.w
                          + a1.x * s1.x + a1.y * s1.y + a1.z * s1.z + a1.w * s1.w;
#pragma unroll
                for (int o = 16; o > 0; o >>= 1)
                    acc += __shfl_down_sync(0xffffffffu, acc, o);
                if (lane == 0) g_ST[(width + cc) * Sd + i] = acc;
            }
            grid_sync(5 + k, 64);
            width <<= 1;
        }

        for (int e = wgid; e < Td * MINd; e += 512) {
            const int tau = e >> 6, m = e & 63;
            const float4* b4 = (const float4*)(Bssm + (size_t)m * Sd);
            const float4* s4 = (const float4*)(g_ST + (127 - tau) * Sd);
            float4 a0 = b4[2 * lane], a1 = b4[2 * lane + 1];
            float4 s0 = s4[2 * lane], s1 = s4[2 * lane + 1];
            float acc = a0.x * s0.x + a0.y * s0.y + a0.z * s0.z + a0.w * s0.w
                      + a1.x * s1.x + a1.y * s1.y + a1.z * s1.z + a1.w * s1.w;
#pragma unroll
            for (int o = 16; o > 0; o >>= 1)
                acc += __shfl_down_sync(0xffffffffu, acc, o);
            if (lane == 0) g_M[tau * MINd + m] = acc;
        }
        __threadfence();
        __syncthreads();
        if (t == 0) atomicAdd((int*)&g_sync[15], 1);   // release M
    } else if (vb < 320) {
        // ================= gemm1 (f32x2 SIMT, 128x128 tile) =================
        float* xs = (float*)dynsm;               // [128][36]
        float* ws = (float*)dynsm + 128 * 36;    // [32][128]
        const int vg = vb - 64;
        const int u = vg & 1;
        const int b0 = (vg >> 1) * 128;
        const int tx = t & 15;
        const int ty = t >> 4;
        const float* w1u = w1 + (size_t)u * KINd * H1d;
        const float* b1u = b1 + (size_t)u * H1d;

        ull acc2[8][4];
#pragma unroll
        for (int r = 0; r < 8; ++r)
#pragma unroll
            for (int j = 0; j < 4; ++j) acc2[r][j] = 0ULL;

        for (int k0 = 0; k0 < KINd; k0 += 32) {
            for (int q = t; q < 1024; q += 256) {
                int r = q >> 3, c = q & 7;
                *(float4*)&xs[r * 36 + c * 4] =
                    *(const float4*)(x + (size_t)(b0 + r) * KINd + k0 + c * 4);
            }
            for (int q = t; q < 1024; q += 256) {
                int r = q >> 5, c = q & 31;
                *(float4*)&ws[r * 128 + c * 4] =
                    *(const float4*)(w1u + (size_t)(k0 + r) * H1d + c * 4);
            }
            __syncthreads();
#pragma unroll 4
            for (int kk = 0; kk < 32; ++kk) {
                ull ap[8];
#pragma unroll
                for (int r = 0; r < 8; ++r) {
                    float a = xs[(ty * 8 + r) * 36 + kk];
                    ap[r] = pack2(a, a);
                }
                ulonglong2 wa = *(const ulonglong2*)&ws[kk * 128 + tx * 8];
                ulonglong2 wb = *(const ulonglong2*)&ws[kk * 128 + tx * 8 + 4];
#pragma unroll
                for (int r = 0; r < 8; ++r) {
                    ffma2(acc2[r][0], ap[r], wa.x);
                    ffma2(acc2[r][1], ap[r], wa.y);
                    ffma2(acc2[r][2], ap[r], wb.x);
                    ffma2(acc2[r][3], ap[r], wb.y);
                }
            }
            __syncthreads();
        }
#pragma unroll
        for (int r = 0; r < 8; ++r) {
            int b = b0 + ty * 8 + r;
            float* dst = g_h1 + ((size_t)b * 2 + u) * H1d + tx * 8;
#pragma unroll
            for (int j = 0; j < 4; ++j) {
                float lo, hi;
                unpack2(acc2[r][j], lo, hi);
                int n = tx * 8 + 2 * j;
                float v0 = fmaxf(lo + b1u[n], 0.f);
                float v1 = fmaxf(hi + b1u[n + 1], 0.f);
                float2 o2; o2.x = v0; o2.y = v1;
                *(float2*)(dst + 2 * j) = o2;
            }
        }
        __threadfence();
        __syncthreads();
        if (t == 0) g_tdone[vg] = 1;               // release this h1 tile
    } else if (vb < 2368) {
        // ================= mamba: 8 warps, one row each =================
        if (t == 0) {
            while (*(volatile int*)&g_sync[15] < 64) { }
            __threadfence();
        }
        __syncthreads();
        float4* Ms = (float4*)dynsm;     // 2048 float4 = 32 KB
        const float4* Mg = (const float4*)g_M;
        for (int q = t; q < 2048; q += 256) Ms[q] = __ldcg(Mg + q);
        __syncthreads();
        const int warp = t >> 5, lane = t & 31;
        const int b = (vb - 320) * 8 + warp;
        const float4* xr = (const float4*)(xm + (size_t)b * (Td * MINd));
        float acc = 0.f;
#pragma unroll 8
        for (int j = lane; j < 2048; j += 32) {
            float4 xv = xr[j];
            float4 mv = Ms[j];
            acc += xv.x * mv.x + xv.y * mv.y + xv.z * mv.z + xv.w * mv.w;
        }
#pragma unroll
        for (int o = 16; o > 0; o >>= 1) acc += __shfl_down_sync(0xffffffffu, acc, o);
        if (lane == 0) out[b] = wm[0] * acc;
    } else {
        // ================= gemm2: waits on its h1 producer tile =============
        float* hs  = (float*)dynsm;              // [64][65]
        float* w2s = (float*)dynsm + 64 * 65;    // [64][64]
        const int vg2 = vb - 2368;
        const int u = vg2 & 1;
        const int b0 = (vg2 >> 1) * 64;
        const int flag = ((b0 >> 7) << 1) | u;   // producer gemm1 vg
        if (t == 0) {
            while (*(volatile int*)&g_tdone[flag] == 0) { }
            __threadfence();
        }
        __syncthreads();

        const int tx = t & 15;
        const int ty = t >> 4;
        const float* w2u = w2 + (size_t)u * H1d * H2d;

        float acc[4][4];
#pragma unroll
        for (int i = 0; i < 4; ++i)
#pragma unroll
            for (int j = 0; j < 4; ++j) acc[i][j] = 0.f;

        for (int k0 = 0; k0 < H1d; k0 += 64) {
            for (int q = t; q < 1024; q += 256) {
                int r = q >> 4, c = q & 15;
                float4 v = *(const float4*)(g_h1 + ((size_t)(b0 + r) * 2 + u) * H1d + k0 + c * 4);
                hs[r * 65 + c * 4 + 0] = v.x; hs[r * 65 + c * 4 + 1] = v.y;
                hs[r * 65 + c * 4 + 2] = v.z; hs[r * 65 + c * 4 + 3] = v.w;
            }
            for (int q = t; q < 1024; q += 256) {
                int r = q >> 4, c = q & 15;
                *(float4*)&w2s[r * 64 + c * 4] = *(const float4*)(w2u + (size_t)(k0 + r) * H2d + c * 4);
            }
            __syncthreads();
#pragma unroll 8
            for (int f = 0; f < 64; ++f) {
                float4 w = *(float4*)&w2s[f * 64 + tx * 4];
                float a0 = hs[(ty * 4 + 0) * 65 + f];
                float a1 = hs[(ty * 4 + 1) * 65 + f];
                float a2 = hs[(ty * 4 + 2) * 65 + f];
                float a3 = hs[(ty * 4 + 3) * 65 + f];
                acc[0][0] += a0 * w.x; acc[0][1] += a0 * w.y; acc[0][2] += a0 * w.z; acc[0][3] += a0 * w.w;
                acc[1][0] += a1 * w.x; acc[1][1] += a1 * w.y; acc[1][2] += a1 * w.z; acc[1][3] += a1 * w.w;
                acc[2][0] += a2 * w.x; acc[2][1] += a2 * w.y; acc[2][2] += a2 * w.z; acc[2][3] += a2 * w.w;
                acc[3][0] += a3 * w.x; acc[3][1] += a3 * w.y; acc[3][2] += a3 * w.z; acc[3][3] += a3 * w.w;
            }
            __syncthreads();
        }
#pragma unroll
        for (int i = 0; i < 4; ++i) {
            int b = b0 + ty * 4 + i;
#pragma unroll
            for (int j = 0; j < 4; ++j) {
                int g = tx * 4 + j;
                float v = acc[i][j] + b2[u * H2d + g];
                g_h2[((size_t)b * 2 + u) * H2d + g] = fmaxf(v, 0.f);
            }
        }
    }
}

// inner[b,u] = sum_i softplus(h2.Ww[:,i]+bw[i])*x[b,i] + h2.sWb + sbb
// 64-row tiles, grid (2, 256) — 52.7 KB smem, 4 CTA/SM.
__global__ void __launch_bounds__(256) stage2_kernel(const float* __restrict__ x,
                                                     const float* __restrict__ ww,
                                                     const float* __restrict__ bw) {
    extern __shared__ char dynsm[];
    float* h2tf = (float*)dynsm;           // [64 g][68 rows]
    float* wws  = h2tf + 64 * 68;          // [64 g][68 i]
    float* xsh  = wws + 64 * 68;           // [64 rows][68 i]
    float* bws  = xsh + 64 * 68;           // [64]
    float* sWbs = bws + 64;                // [64]
    const int u = blockIdx.x;
    const int b0 = blockIdx.y * 64;
    const int t = threadIdx.x;
    const int tx = t & 15;   // 4 i-cols each
    const int ty = t >> 4;   // 4 rows each
    const float* wwu = ww + (size_t)u * H2d * KINd;
    const float* bwu = bw + (size_t)u * KINd;

    if (t < 64) sWbs[t] = g_sWb[u * H2d + t];
    for (int q = t; q < 1024; q += 256) {
        int r = q & 63, gq = (q >> 6) * 4;
        float4 v = *(const float4*)(g_h2 + ((size_t)(b0 + r) * 2 + u) * H2d + gq);
        h2tf[(gq + 0) * 68 + r] = v.x;
        h2tf[(gq + 1) * 68 + r] = v.y;
        h2tf[(gq + 2) * 68 + r] = v.z;
        h2tf[(gq + 3) * 68 + r] = v.w;
    }
    __syncthreads();

    ull acc2[2][4];
    float part[4] = {0.f, 0.f, 0.f, 0.f};

    for (int it = 0; it < 16; ++it) {
        int i0 = it * 64;
        __syncthreads();
        for (int q = t; q < 1024; q += 256) {
            int r = q >> 4, c = q & 15;
            *(float4*)&wws[r * 68 + c * 4] =
                *(const float4*)(wwu + (size_t)r * KINd + i0 + c * 4);
        }
        for (int q = t; q < 1024; q += 256) {
            int r = q >> 4, c = q & 15;
            *(float4*)&xsh[r * 68 + c * 4] =
                *(const float4*)(x + (size_t)(b0 + r) * KINd + i0 + c * 4);
        }
        if (t < 16) *(float4*)&bws[t * 4] = *(const float4*)(bwu + i0 + t * 4);
        __syncthreads();

#pragma unroll
        for (int rp = 0; rp < 2; ++rp)
#pragma unroll
            for (int j = 0; j < 4; ++j) acc2[rp][j] = 0ULL;

#pragma unroll 8
        for (int g = 0; g < 64; ++g) {
            ulonglong2 ha = *(const ulonglong2*)(h2tf + g * 68 + ty * 4);
            float4 wv = *(const float4*)&wws[g * 68 + tx * 4];
            ull w0 = pack2(wv.x, wv.x), w1p = pack2(wv.y, wv.y);
            ull w2p = pack2(wv.z, wv.z), w3p = pack2(wv.w, wv.w);
            ffma2(acc2[0][0], ha.x, w0); ffma2(acc2[0][1], ha.x, w1p);
            ffma2(acc2[0][2], ha.x, w2p); ffma2(acc2[0][3], ha.x, w3p);
            ffma2(acc2[1][0], ha.y, w0); ffma2(acc2[1][1], ha.y, w1p);
            ffma2(acc2[1][2], ha.y, w2p); ffma2(acc2[1][3], ha.y, w3p);
        }

#pragma unroll
        for (int j = 0; j < 4; ++j) {
            float bwv = bws[tx * 4 + j];
#pragma unroll
            for (int rp = 0; rp < 2; ++rp) {
                float s0, s1;
                unpack2(acc2[rp][j], s0, s1);
                float p0 = sp_poly(s0 + bwv);
                float p1 = sp_poly(s1 + bwv);
                part[2 * rp]     += p0 * xsh[(ty * 4 + 2 * rp) * 68 + tx * 4 + j];
                part[2 * rp + 1] += p1 * xsh[(ty * 4 + 2 * rp + 1) * 68 + tx * 4 + j];
            }
        }
    }

#pragma unroll
    for (int gg = 0; gg < 4; ++gg) {
        int g = tx * 4 + gg;
        float swv = sWbs[g];
#pragma unroll
        for (int r = 0; r < 4; ++r)
            part[r] += h2tf[g * 68 + ty * 4 + r] * swv;
    }
#pragma unroll
    for (int r = 0; r < 4; ++r)
#pragma unroll
        for (int o = 8; o > 0; o >>= 1)
            part[r] += __shfl_down_sync(0xffffffffu, part[r], o, 16);
    if (tx == 0) {
        float sbbv = g_sbb[u];
#pragma unroll
        for (int r = 0; r < 4; ++r)
            g_inner[(size_t)(b0 + ty * 4 + r) * 2 + u] = part[r] + sbbv;
    }
}

// outer MLP: out[b] += wk * kan_out[b]; thread = (b, v, f-half)
__global__ void __launch_bounds__(512) outer_kernel(const float* __restrict__ ow1,
                                                    const float* __restrict__ ob1,
                                                    const float* __restrict__ ow2,
                                                    const float* __restrict__ ob2,
                                                    const float* __restrict__ oww,
                                                    const float* __restrict__ obw,
                                                    const float* __restrict__ owb,
                                                    const float* __restrict__ obb,
                                                    const float* __restrict__ wk,
                                                    float* __restrict__ out) {
    extern __shared__ char dynsm[];
    float* OW2f = (float*)dynsm;   // [2][128][68]
    __shared__ float w1as[2][128], w1bs[2][128], b1s[2][128];
    __shared__ float ob2s[2][64], owws[2][64], owbs[2][64];
    const int t = threadIdx.x;
    const int bl = t >> 2;
    const int v = (t >> 1) & 1;
    const int hf = t & 1;
    const int b = blockIdx.x * 128 + bl;

    for (int q = t; q < 4096; q += 512) {
        int vv = q >> 11, f = (q >> 4) & 127, c = q & 15;
        *(float4*)&OW2f[(vv * 128 + f) * 68 + c * 4] =
            *(const float4*)(ow2 + ((size_t)vv * 128 + f) * 64 + c * 4);
    }
    if (t < 256) {
        int vv = t >> 7, f = t & 127;
        w1as[vv][f] = ow1[(vv * 2 + 0) * 128 + f];
        w1bs[vv][f] = ow1[(vv * 2 + 1) * 128 + f];
        b1s[vv][f]  = ob1[vv * 128 + f];
    }
    if (t < 128) {
        int vv = t >> 6, j = t & 63;
        ob2s[vv][j] = ob2[vv * 64 + j];
        owws[vv][j] = oww[vv * 64 + j];
        owbs[vv][j] = owb[vv * 64 + j];
    }
    __syncthreads();

    const float i0 = g_inner[(size_t)b * 2 + 0];
    const float i1 = g_inner[(size_t)b * 2 + 1];

    ull g2a[32];
#pragma unroll
    for (int j = 0; j < 32; ++j)
        g2a[j] = (hf == 0) ? pack2(ob2s[v][2 * j], ob2s[v][2 * j + 1]) : 0ULL;

    const float* OW2v = OW2f + v * 128 * 68;
#pragma unroll 2
    for (int ff = 0; ff < 64; ++ff) {
        int f = hf * 64 + ff;
        float g1f = fmaxf(fmaf(i0, w1as[v][f], fmaf(i1, w1bs[v][f], b1s[v][f])), 0.f);
        ull g1p = pack2(g1f, g1f);
        const ull* row = (const ull*)(OW2v + f * 68);
#pragma unroll
        for (int j = 0; j < 32; ++j) ffma2(g2a[j], g1p, row[j]);
    }
#pragma unroll
    for (int j = 0; j < 32; ++j) {
        ull o = __shfl_xor_sync(0xffffffffu, g2a[j], 1);
        add2(g2a[j], o);
    }
    float sw = 0.f, sb = 0.f;
#pragma unroll
    for (int j = 0; j < 32; ++j) {
        float a, c2;
        unpack2(g2a[j], a, c2);
        a = fmaxf(a, 0.f); c2 = fmaxf(c2, 0.f);
        sw += a * owws[v][2 * j] + c2 * owws[v][2 * j + 1];
        sb += a * owbs[v][2 * j] + c2 * owbs[v][2 * j + 1];
    }
    float wout = sp_poly(sw + obw[v]);
    float bout = sb + obb[v];
    float term = wout * (i0 + i1) + 2.f * bout;
    term += __shfl_xor_sync(0xffffffffu, term, 2);
    if ((t & 3) == 0) out[b] += wk[0] * term;
}

extern "C" void kernel_launch(void* const* d_in, const int* in_sizes, int n_in,
                              void* d_out, int out_size) {
    const float* x_kan   = (const float*)d_in[0];
    const float* x_mamba = (const float*)d_in[1];
    const float* in_w1 = (const float*)d_in[2];
    const float* in_b1 = (const float*)d_in[3];
    const float* in_w2 = (const float*)d_in[4];
    const float* in_b2 = (const float*)d_in[5];
    const float* in_ww = (const float*)d_in[6];
    const float* in_bw = (const float*)d_in[7];
    const float* in_wb = (const float*)d_in[8];
    const float* in_bb = (const float*)d_in[9];
    const float* out_w1 = (const float*)d_in[10];
    const float* out_b1 = (const float*)d_in[11];
    const float* out_w2 = (const float*)d_in[12];
    const float* out_b2 = (const float*)d_in[13];
    const float* out_ww = (const float*)d_in[14];
    const float* out_bw = (const float*)d_in[15];
    const float* out_wb = (const float*)d_in[16];
    const float* out_bb = (const float*)d_in[17];
    const float* A      = (const float*)d_in[18];
    const float* B_ssm  = (const float*)d_in[19];
    const float* C_ssm  = (const float*)d_in[20];
    const float* wk     = (const float*)d_in[21];
    const float* wm     = (const float*)d_in[22];
    float* out = (float*)d_out;

    const int MGSMEM = (256 * 34 + 256 * 36) * 4;                       // 71680 (prelude max)
    const int S2SMEM = (3 * 64 * 68 + 64 + 64) * 4;                     // 52736
    const int OSMEM  = 2 * 128 * 68 * 4;                                 // 69632
    cudaFuncSetAttribute(mega_kernel, cudaFuncAttributeMaxDynamicSharedMemorySize, MGSMEM);
    cudaFuncSetAttribute(stage2_kernel, cudaFuncAttributeMaxDynamicSharedMemorySize, S2SMEM);
    cudaFuncSetAttribute(outer_kernel, cudaFuncAttributeMaxDynamicSharedMemorySize, OSMEM);

    ksums_kernel<<<130, 32>>>(in_wb, in_bb);                          // 1 (+ctr/flag reset)
    mega_kernel<<<64 + 256 + 2048 + 512, 256, MGSMEM>>>(x_kan, in_w1, in_b1,
                                                        x_mamba, wm,
                                                        A, B_ssm, C_ssm,
                                                        in_w2, in_b2, out); // 2
    stage2_kernel<<<dim3(2, Bn / 64), 256, S2SMEM>>>(x_kan, in_ww, in_bw);  // 3
    outer_kernel<<<Bn / 128, 512, OSMEM>>>(out_w1, out_b1, out_w2, out_b2,
                                           out_ww, out_bw, out_wb, out_bb, wk, out); // 4 (profiled)
}

// round 13
// speedup vs baseline: 1.7026x; 1.2083x over previous
#include <cuda_runtime.h>
#include <math.h>
#include <cstdint>

#define Bn    16384
#define KINd  1024
#define MINd  64
#define Sd    256
#define Td    128
#define H1d   128
#define H2d   64

typedef unsigned long long ull;

// ------------------------- scratch (device globals; no allocs) --------------
static __device__ __align__(16) float g_Pw[6 * Sd * Sd];   // A^2,4,8,16,32,64
static __device__ __align__(16) float g_ST[128 * Sd];      // S^T: row n = A^n c
static __device__ __align__(16) float g_M[Td * MINd];
static __device__ __align__(16) float g_h1[(size_t)Bn * 2 * H1d];   // 16 MB
static __device__ __align__(16) float g_h2[(size_t)Bn * 2 * H2d];   // 8 MB
static __device__ __align__(16) float g_inner[(size_t)Bn * 2];
static __device__ float g_sWb[2 * H2d];
static __device__ float g_sbb[2];
static __device__ volatile int g_sync[16];    // [15] = M-ready counter
static __device__ volatile int g_tdone[256];  // gemm1 tile-done flags

// ---- FMA-only softplus (no MUFU) -------------------------------------------
__device__ __forceinline__ float sp_poly(float s) {
    float t = fmaxf(-fabsf(s), -17.f);
    float z = t * 1.44269504f;
    int   ni = __float2int_rn(z);
    float f = z - (float)ni;
    float p = 1.33335581e-3f;
    p = fmaf(p, f, 9.61812911e-3f);
    p = fmaf(p, f, 5.55041087e-2f);
    p = fmaf(p, f, 2.40226507e-1f);
    p = fmaf(p, f, 6.93147181e-1f);
    p = fmaf(p, f, 1.f);
    float y = __int_as_float((ni + 127) << 23) * p;
    float v = 2.f + y;
    float r0 = fmaf(-0.1716f, v, 0.8249f);
    r0 = r0 * fmaf(-v, r0, 2.f);
    r0 = r0 * fmaf(-v, r0, 2.f);
    float r  = y * r0;
    float r2 = r * r;
    float q = fmaf(r2, 0.28571429f, 0.4f);
    q = fmaf(r2, q, 0.66666667f);
    q = fmaf(r2, q, 2.f);
    return fmaxf(s, 0.f) + r * q;
}

// ---- packed f32x2 helpers ---------------------------------------------------
__device__ __forceinline__ void ffma2(ull& d, ull a, ull b) {
    asm("fma.rn.f32x2 %0, %1, %2, %0;" : "+l"(d) : "l"(a), "l"(b));
}
__device__ __forceinline__ ull pack2(float lo, float hi) {
    ull r; asm("mov.b64 %0, {%1, %2};" : "=l"(r) : "f"(lo), "f"(hi)); return r;
}
__device__ __forceinline__ void unpack2(ull v, float& lo, float& hi) {
    asm("mov.b64 {%0, %1}, %2;" : "=f"(lo), "=f"(hi) : "l"(v));
}

// ---- resident-grid sync among prelude blocks (counters reset by ksums) ------
__device__ __forceinline__ void grid_sync(int s, int n) {
    __threadfence();
    __syncthreads();
    if (threadIdx.x == 0) {
        atomicAdd((int*)&g_sync[s], 1);
        while (*(volatile int*)&g_sync[s] < n) { }
        __threadfence();
    }
    __syncthreads();
}

// row-sums of in_wb / in_bb (bias-collapse) + counter/flag reset for replays
__global__ void ksums_kernel(const float* __restrict__ wb,
                             const float* __restrict__ bb) {
    int r = blockIdx.x, lane = threadIdx.x;
    if (r == 0) {
        if (lane == 0)
#pragma unroll
            for (int s = 0; s < 16; ++s) g_sync[s] = 0;
        for (int i = lane; i < 256; i += 32) g_tdone[i] = 0;
    }
    float s = 0.f;
    if (r < 128) {
        const float* row = wb + (size_t)r * KINd;
        for (int i = lane; i < KINd; i += 32) s += row[i];
    } else if (r < 130) {
        const float* row = bb + (size_t)(r - 128) * KINd;
        for (int i = lane; i < KINd; i += 32) s += row[i];
    }
#pragma unroll
    for (int o = 16; o > 0; o >>= 1) s += __shfl_down_sync(0xffffffffu, s, o);
    if (lane == 0) {
        if (r < 128) g_sWb[r] = s;
        else if (r < 130) g_sbb[r - 128] = s;
    }
}

// ---------- MEGA kernel ------------------------------------------------------
// blocks 0..63     : SSM prelude (A powers -> Krylov doubling -> M)
// blocks 64..319   : gemm1  h1 = relu(x @ W1[u] + b1[u])  (sets tile flags)
// blocks 320..2367 : mamba  out[b] = wm * <x_mamba[b], M> (waits on M-ready)
// blocks 2368..2879: gemm2  h2 = relu(h1 @ W2[u] + b2[u]) (waits on tile flag)
__global__ void __launch_bounds__(256) mega_kernel(const float* __restrict__ x,
                                                   const float* __restrict__ w1,
                                                   const float* __restrict__ b1,
                                                   const float* __restrict__ xm,
                                                   const float* __restrict__ wm,
                                                   const float* __restrict__ A,
                                                   const float* __restrict__ Bssm,
                                                   const float* __restrict__ Cssm,
                                                   const float* __restrict__ w2,
                                                   const float* __restrict__ b2,
                                                   float* __restrict__ out) {
    extern __shared__ char dynsm[];
    const int vb = blockIdx.x;
    const int t = threadIdx.x;

    if (vb < 64) {
        // ================= prelude =================
        float* As = (float*)dynsm;            // [256][34] transposed L tile
        float* Bs = (float*)dynsm + 256 * 34; // [256][36] R tile
        const int tx = t & 15, ty = t >> 4;
        const int rb = (vb >> 3) * 32, cb = (vb & 7) * 32;
        const int warp = t >> 5, lane = t & 31;
        const int wgid = vb * 8 + warp;       // 0..511

        if (vb == 0) g_ST[t] = Cssm[t];       // S^T row 0 = c

#pragma unroll
        for (int s = 0; s < 6; ++s) {
            const float* L = (s == 0) ? A : g_Pw + (size_t)(s - 1) * Sd * Sd;
            float* C = g_Pw + (size_t)s * Sd * Sd;
            for (int q = t; q < 2048; q += 256) {
                int i = q >> 6, k4 = (q & 63) * 4;
                float4 v = *(const float4*)(L + (size_t)(rb + i) * Sd + k4);
                As[(k4 + 0) * 34 + i] = v.x;
                As[(k4 + 1) * 34 + i] = v.y;
                As[(k4 + 2) * 34 + i] = v.z;
                As[(k4 + 3) * 34 + i] = v.w;
            }
            for (int q = t; q < 2048; q += 256) {
                int k = q >> 3, j4 = (q & 7) * 4;
                *(float4*)&Bs[k * 36 + j4] = *(const float4*)(L + (size_t)k * Sd + cb + j4);
            }
            __syncthreads();
            float c00 = 0.f, c01 = 0.f, c10 = 0.f, c11 = 0.f;
#pragma unroll 8
            for (int k = 0; k < 256; ++k) {
                float2 av = *(float2*)&As[k * 34 + ty * 2];
                float2 bv = *(float2*)&Bs[k * 36 + tx * 2];
                c00 += av.x * bv.x; c01 += av.x * bv.y;
                c10 += av.y * bv.x; c11 += av.y * bv.y;
            }
            C[(size_t)(rb + ty * 2) * Sd + cb + tx * 2]         = c00;
            C[(size_t)(rb + ty * 2) * Sd + cb + tx * 2 + 1]     = c01;
            C[(size_t)(rb + ty * 2 + 1) * Sd + cb + tx * 2]     = c10;
            C[(size_t)(rb + ty * 2 + 1) * Sd + cb + tx * 2 + 1] = c11;
            if (s < 5) grid_sync(s, 64);
        }

        int width = 1;
#pragma unroll
        for (int k = 0; k < 7; ++k) {
            const float* Pb = (k == 0) ? A : g_Pw + (size_t)(k - 1) * Sd * Sd;
            const int nout = Sd * width;
            for (int e = wgid; e < nout; e += 512) {
                const int cc = e >> 8, i = e & 255;
                const float4* p4 = (const float4*)(Pb + (size_t)i * Sd);
                const float4* s4 = (const float4*)(g_ST + cc * Sd);
                float4 a0 = p4[2 * lane], a1 = p4[2 * lane + 1];
                float4 s0 = s4[2 * lane], s1 = s4[2 * lane + 1];
                float acc = a0.x * s0.x + a0.y * s0.y + a0.z * s0.z + a0.w * s0.w
                          + a1.x * s1.x + a1.y * s1.y + a1.z * s1.z + a1.w * s1.w;
#pragma unroll
                for (int o = 16; o > 0; o >>= 1)
                    acc += __shfl_down_sync(0xffffffffu, acc, o);
                if (lane == 0) g_ST[(width + cc) * Sd + i] = acc;
            }
            grid_sync(5 + k, 64);
            width <<= 1;
        }

        for (int e = wgid; e < Td * MINd; e += 512) {
            const int tau = e >> 6, m = e & 63;
            const float4* b4 = (const float4*)(Bssm + (size_t)m * Sd);
            const float4* s4 = (const float4*)(g_ST + (127 - tau) * Sd);
            float4 a0 = b4[2 * lane], a1 = b4[2 * lane + 1];
            float4 s0 = s4[2 * lane], s1 = s4[2 * lane + 1];
            float acc = a0.x * s0.x + a0.y * s0.y + a0.z * s0.z + a0.w * s0.w
                      + a1.x * s1.x + a1.y * s1.y + a1.z * s1.z + a1.w * s1.w;
#pragma unroll
            for (int o = 16; o > 0; o >>= 1)
                acc += __shfl_down_sync(0xffffffffu, acc, o);
            if (lane == 0) g_M[tau * MINd + m] = acc;
        }
        __threadfence();
        __syncthreads();
        if (t == 0) atomicAdd((int*)&g_sync[15], 1);   // release M
    } else if (vb < 320) {
        // ================= gemm1 (f32x2 SIMT, 128x128 tile) =================
        float* xs = (float*)dynsm;               // [128][36]
        float* ws = (float*)dynsm + 128 * 36;    // [32][128]
        const int vg = vb - 64;
        const int u = vg & 1;
        const int b0 = (vg >> 1) * 128;
        const int tx = t & 15;
        const int ty = t >> 4;
        const float* w1u = w1 + (size_t)u * KINd * H1d;
        const float* b1u = b1 + (size_t)u * H1d;

        ull acc2[8][4];
#pragma unroll
        for (int r = 0; r < 8; ++r)
#pragma unroll
            for (int j = 0; j < 4; ++j) acc2[r][j] = 0ULL;

        for (int k0 = 0; k0 < KINd; k0 += 32) {
            for (int q = t; q < 1024; q += 256) {
                int r = q >> 3, c = q & 7;
                *(float4*)&xs[r * 36 + c * 4] =
                    *(const float4*)(x + (size_t)(b0 + r) * KINd + k0 + c * 4);
            }
            for (int q = t; q < 1024; q += 256) {
                int r = q >> 5, c = q & 31;
                *(float4*)&ws[r * 128 + c * 4] =
                    *(const float4*)(w1u + (size_t)(k0 + r) * H1d + c * 4);
            }
            __syncthreads();
#pragma unroll 4
            for (int kk = 0; kk < 32; ++kk) {
                ull ap[8];
#pragma unroll
                for (int r = 0; r < 8; ++r) {
                    float a = xs[(ty * 8 + r) * 36 + kk];
                    ap[r] = pack2(a, a);
                }
                ulonglong2 wa = *(const ulonglong2*)&ws[kk * 128 + tx * 8];
                ulonglong2 wb = *(const ulonglong2*)&ws[kk * 128 + tx * 8 + 4];
#pragma unroll
                for (int r = 0; r < 8; ++r) {
                    ffma2(acc2[r][0], ap[r], wa.x);
                    ffma2(acc2[r][1], ap[r], wa.y);
                    ffma2(acc2[r][2], ap[r], wb.x);
                    ffma2(acc2[r][3], ap[r], wb.y);
                }
            }
            __syncthreads();
        }
#pragma unroll
        for (int r = 0; r < 8; ++r) {
            int b = b0 + ty * 8 + r;
            float* dst = g_h1 + ((size_t)b * 2 + u) * H1d + tx * 8;
#pragma unroll
            for (int j = 0; j < 4; ++j) {
                float lo, hi;
                unpack2(acc2[r][j], lo, hi);
                int n = tx * 8 + 2 * j;
                float v0 = fmaxf(lo + b1u[n], 0.f);
                float v1 = fmaxf(hi + b1u[n + 1], 0.f);
                float2 o2; o2.x = v0; o2.y = v1;
                *(float2*)(dst + 2 * j) = o2;
            }
        }
        __threadfence();
        __syncthreads();
        if (t == 0) g_tdone[vg] = 1;               // release this h1 tile
    } else if (vb < 2368) {
        // ================= mamba: 8 warps, one row each =================
        if (t == 0) {
            while (*(volatile int*)&g_sync[15] < 64) { }
            __threadfence();
        }
        __syncthreads();
        float4* Ms = (float4*)dynsm;     // 2048 float4 = 32 KB
        const float4* Mg = (const float4*)g_M;
        for (int q = t; q < 2048; q += 256) Ms[q] = __ldcg(Mg + q);
        __syncthreads();
        const int warp = t >> 5, lane = t & 31;
        const int b = (vb - 320) * 8 + warp;
        const float4* xr = (const float4*)(xm + (size_t)b * (Td * MINd));
        float acc = 0.f;
#pragma unroll 8
        for (int j = lane; j < 2048; j += 32) {
            float4 xv = xr[j];
            float4 mv = Ms[j];
            acc += xv.x * mv.x + xv.y * mv.y + xv.z * mv.z + xv.w * mv.w;
        }
#pragma unroll
        for (int o = 16; o > 0; o >>= 1) acc += __shfl_down_sync(0xffffffffu, acc, o);
        if (lane == 0) out[b] = wm[0] * acc;
    } else {
        // ================= gemm2: waits on its h1 producer tile =============
        float* hs  = (float*)dynsm;              // [64][65]
        float* w2s = (float*)dynsm + 64 * 65;    // [64][64]
        const int vg2 = vb - 2368;
        const int u = vg2 & 1;
        const int b0 = (vg2 >> 1) * 64;
        const int flag = ((b0 >> 7) << 1) | u;   // producer gemm1 vg
        if (t == 0) {
            while (*(volatile int*)&g_tdone[flag] == 0) { }
            __threadfence();
        }
        __syncthreads();

        const int tx = t & 15;
        const int ty = t >> 4;
        const float* w2u = w2 + (size_t)u * H1d * H2d;

        float acc[4][4];
#pragma unroll
        for (int i = 0; i < 4; ++i)
#pragma unroll
            for (int j = 0; j < 4; ++j) acc[i][j] = 0.f;

        for (int k0 = 0; k0 < H1d; k0 += 64) {
            for (int q = t; q < 1024; q += 256) {
                int r = q >> 4, c = q & 15;
                float4 v = *(const float4*)(g_h1 + ((size_t)(b0 + r) * 2 + u) * H1d + k0 + c * 4);
                hs[r * 65 + c * 4 + 0] = v.x; hs[r * 65 + c * 4 + 1] = v.y;
                hs[r * 65 + c * 4 + 2] = v.z; hs[r * 65 + c * 4 + 3] = v.w;
            }
            for (int q = t; q < 1024; q += 256) {
                int r = q >> 4, c = q & 15;
                *(float4*)&w2s[r * 64 + c * 4] = *(const float4*)(w2u + (size_t)(k0 + r) * H2d + c * 4);
            }
            __syncthreads();
#pragma unroll 8
            for (int f = 0; f < 64; ++f) {
                float4 w = *(float4*)&w2s[f * 64 + tx * 4];
                float a0 = hs[(ty * 4 + 0) * 65 + f];
                float a1 = hs[(ty * 4 + 1) * 65 + f];
                float a2 = hs[(ty * 4 + 2) * 65 + f];
                float a3 = hs[(ty * 4 + 3) * 65 + f];
                acc[0][0] += a0 * w.x; acc[0][1] += a0 * w.y; acc[0][2] += a0 * w.z; acc[0][3] += a0 * w.w;
                acc[1][0] += a1 * w.x; acc[1][1] += a1 * w.y; acc[1][2] += a1 * w.z; acc[1][3] += a1 * w.w;
                acc[2][0] += a2 * w.x; acc[2][1] += a2 * w.y; acc[2][2] += a2 * w.z; acc[2][3] += a2 * w.w;
                acc[3][0] += a3 * w.x; acc[3][1] += a3 * w.y; acc[3][2] += a3 * w.z; acc[3][3] += a3 * w.w;
            }
            __syncthreads();
        }
#pragma unroll
        for (int i = 0; i < 4; ++i) {
            int b = b0 + ty * 4 + i;
#pragma unroll
            for (int j = 0; j < 4; ++j) {
                int g = tx * 4 + j;
                float v = acc[i][j] + b2[u * H2d + g];
                g_h2[((size_t)b * 2 + u) * H2d + g] = fmaxf(v, 0.f);
            }
        }
    }
}

// inner[b,u] = sum_i softplus(h2.Ww[:,i]+bw[i])*x[b,i] + h2.sWb + sbb
// 64-row tiles, grid (2, 256) — 52.7 KB smem, 4 CTA/SM.
__global__ void __launch_bounds__(256) stage2_kernel(const float* __restrict__ x,
                                                     const float* __restrict__ ww,
                                                     const float* __restrict__ bw) {
    extern __shared__ char dynsm[];
    float* h2tf = (float*)dynsm;           // [64 g][68 rows]
    float* wws  = h2tf + 64 * 68;          // [64 g][68 i]
    float* xsh  = wws + 64 * 68;           // [64 rows][68 i]
    float* bws  = xsh + 64 * 68;           // [64]
    float* sWbs = bws + 64;                // [64]
    const int u = blockIdx.x;
    const int b0 = blockIdx.y * 64;
    const int t = threadIdx.x;
    const int tx = t & 15;
    const int ty = t >> 4;
    const float* wwu = ww + (size_t)u * H2d * KINd;
    const float* bwu = bw + (size_t)u * KINd;

    if (t < 64) sWbs[t] = g_sWb[u * H2d + t];
    for (int q = t; q < 1024; q += 256) {
        int r = q & 63, gq = (q >> 6) * 4;
        float4 v = *(const float4*)(g_h2 + ((size_t)(b0 + r) * 2 + u) * H2d + gq);
        h2tf[(gq + 0) * 68 + r] = v.x;
        h2tf[(gq + 1) * 68 + r] = v.y;
        h2tf[(gq + 2) * 68 + r] = v.z;
        h2tf[(gq + 3) * 68 + r] = v.w;
    }
    __syncthreads();

    ull acc2[2][4];
    float part[4] = {0.f, 0.f, 0.f, 0.f};

    for (int it = 0; it < 16; ++it) {
        int i0 = it * 64;
        __syncthreads();
        for (int q = t; q < 1024; q += 256) {
            int r = q >> 4, c = q & 15;
            *(float4*)&wws[r * 68 + c * 4] =
                *(const float4*)(wwu + (size_t)r * KINd + i0 + c * 4);
        }
        for (int q = t; q < 1024; q += 256) {
            int r = q >> 4, c = q & 15;
            *(float4*)&xsh[r * 68 + c * 4] =
                *(const float4*)(x + (size_t)(b0 + r) * KINd + i0 + c * 4);
        }
        if (t < 16) *(float4*)&bws[t * 4] = *(const float4*)(bwu + i0 + t * 4);
        __syncthreads();

#pragma unroll
        for (int rp = 0; rp < 2; ++rp)
#pragma unroll
            for (int j = 0; j < 4; ++j) acc2[rp][j] = 0ULL;

#pragma unroll 8
        for (int g = 0; g < 64; ++g) {
            ulonglong2 ha = *(const ulonglong2*)(h2tf + g * 68 + ty * 4);
            float4 wv = *(const float4*)&wws[g * 68 + tx * 4];
            ull w0 = pack2(wv.x, wv.x), w1p = pack2(wv.y, wv.y);
            ull w2p = pack2(wv.z, wv.z), w3p = pack2(wv.w, wv.w);
            ffma2(acc2[0][0], ha.x, w0); ffma2(acc2[0][1], ha.x, w1p);
            ffma2(acc2[0][2], ha.x, w2p); ffma2(acc2[0][3], ha.x, w3p);
            ffma2(acc2[1][0], ha.y, w0); ffma2(acc2[1][1], ha.y, w1p);
            ffma2(acc2[1][2], ha.y, w2p); ffma2(acc2[1][3], ha.y, w3p);
        }

#pragma unroll
        for (int j = 0; j < 4; ++j) {
            float bwv = bws[tx * 4 + j];
#pragma unroll
            for (int rp = 0; rp < 2; ++rp) {
                float s0, s1;
                unpack2(acc2[rp][j], s0, s1);
                float p0 = sp_poly(s0 + bwv);
                float p1 = sp_poly(s1 + bwv);
                part[2 * rp]     += p0 * xsh[(ty * 4 + 2 * rp) * 68 + tx * 4 + j];
                part[2 * rp + 1] += p1 * xsh[(ty * 4 + 2 * rp + 1) * 68 + tx * 4 + j];
            }
        }
    }

#pragma unroll
    for (int gg = 0; gg < 4; ++gg) {
        int g = tx * 4 + gg;
        float swv = sWbs[g];
#pragma unroll
        for (int r = 0; r < 4; ++r)
            part[r] += h2tf[g * 68 + ty * 4 + r] * swv;
    }
#pragma unroll
    for (int r = 0; r < 4; ++r)
#pragma unroll
        for (int o = 8; o > 0; o >>= 1)
            part[r] += __shfl_down_sync(0xffffffffu, part[r], o, 16);
    if (tx == 0) {
        float sbbv = g_sbb[u];
#pragma unroll
        for (int r = 0; r < 4; ++r)
            g_inner[(size_t)(b0 + ty * 4 + r) * 2 + u] = part[r] + sbbv;
    }
}

// outer MLP as a tiled batched GEMM: 64 b-rows per block, v-loop inside.
__global__ void __launch_bounds__(256) outer_kernel(const float* __restrict__ ow1,
                                                    const float* __restrict__ ob1,
                                                    const float* __restrict__ ow2,
                                                    const float* __restrict__ ob2,
                                                    const float* __restrict__ oww,
                                                    const float* __restrict__ obw,
                                                    const float* __restrict__ owb,
                                                    const float* __restrict__ obb,
                                                    const float* __restrict__ wk,
                                                    float* __restrict__ out) {
    __shared__ float i0s[64], i1s[64];
    __shared__ float w1af[128], w1bf[128], b1f[128];
    __shared__ float W2s[32 * 68];
    __shared__ float g1s[32 * 68];
    __shared__ float ob2s[64], owws[64], owbs[64];
    const int t = threadIdx.x;
    const int tx = t & 15;   // 4 j-cols each
    const int ty = t >> 4;   // 4 b-rows each
    const int b0 = blockIdx.x * 64;

    if (t < 64) {
        float2 iv = *(const float2*)(g_inner + (size_t)(b0 + t) * 2);
        i0s[t] = iv.x;
        i1s[t] = iv.y;
    }

    float kan[4] = {0.f, 0.f, 0.f, 0.f};

#pragma unroll
    for (int v = 0; v < 2; ++v) {
        __syncthreads();
        if (t < 128) {
            w1af[t] = ow1[(v * 2 + 0) * H1d + t];
            w1bf[t] = ow1[(v * 2 + 1) * H1d + t];
            b1f[t]  = ob1[v * H1d + t];
        } else if (t < 192) {
            int j = t - 128;
            ob2s[j] = ob2[v * H2d + j];
            owws[j] = oww[v * H2d + j];
            owbs[j] = owb[v * H2d + j];
        }
        __syncthreads();

        float acc[4][4];
#pragma unroll
        for (int i = 0; i < 4; ++i)
#pragma unroll
            for (int j = 0; j < 4; ++j) acc[i][j] = 0.f;

        for (int fc = 0; fc < 4; ++fc) {
            const int f0 = fc * 32;
            __syncthreads();
            for (int q = t; q < 2048; q += 256) {
                int f = q >> 6, b = q & 63;
                g1s[f * 68 + b] =
                    fmaxf(fmaf(i0s[b], w1af[f0 + f],
                          fmaf(i1s[b], w1bf[f0 + f], b1f[f0 + f])), 0.f);
            }
            for (int q = t; q < 512; q += 256) {
                int f = q >> 4, c = q & 15;
                *(float4*)&W2s[f * 68 + c * 4] =
                    *(const float4*)(ow2 + ((size_t)v * H1d + f0 + f) * H2d + c * 4);
            }
            __syncthreads();
#pragma unroll 8
            for (int f = 0; f < 32; ++f) {
                float4 w = *(float4*)&W2s[f * 68 + tx * 4];
                float a0 = g1s[f * 68 + ty * 4 + 0];
                float a1 = g1s[f * 68 + ty * 4 + 1];
                float a2 = g1s[f * 68 + ty * 4 + 2];
                float a3 = g1s[f * 68 + ty * 4 + 3];
                acc[0][0] += a0 * w.x; acc[0][1] += a0 * w.y; acc[0][2] += a0 * w.z; acc[0][3] += a0 * w.w;
                acc[1][0] += a1 * w.x; acc[1][1] += a1 * w.y; acc[1][2] += a1 * w.z; acc[1][3] += a1 * w.w;
                acc[2][0] += a2 * w.x; acc[2][1] += a2 * w.y; acc[2][2] += a2 * w.z; acc[2][3] += a2 * w.w;
                acc[3][0] += a3 * w.x; acc[3][1] += a3 * w.y; acc[3][2] += a3 * w.z; acc[3][3] += a3 * w.w;
            }
        }

        // epilogue: per-b sums over this thread's 4 j columns, reduce over tx
        float swp[4], sbp[4];
#pragma unroll
        for (int i = 0; i < 4; ++i) { swp[i] = 0.f; sbp[i] = 0.f; }
#pragma unroll
        for (int j = 0; j < 4; ++j) {
            int jj = tx * 4 + j;
            float bz = ob2s[jj], wwv = owws[jj], wbv = owbs[jj];
#pragma unroll
            for (int i = 0; i < 4; ++i) {
                float g2 = fmaxf(acc[i][j] + bz, 0.f);
                swp[i] += g2 * wwv;
                sbp[i] += g2 * wbv;
            }
        }
#pragma unroll
        for (int i = 0; i < 4; ++i) {
#pragma unroll
            for (int o = 8; o > 0; o >>= 1) {
                swp[i] += __shfl_down_sync(0xffffffffu, swp[i], o, 16);
                sbp[i] += __shfl_down_sync(0xffffffffu, sbp[i], o, 16);
            }
        }
        if (tx == 0) {
            float obwv = obw[v], obbv = obb[v];
#pragma unroll
            for (int i = 0; i < 4; ++i) {
                int b = ty * 4 + i;
                float wout = sp_poly(swp[i] + obwv);
                kan[i] += wout * (i0s[b] + i1s[b]) + 2.f * (sbp[i] + obbv);
            }
        }
    }

    if (tx == 0) {
        float wkv = wk[0];
#pragma unroll
        for (int i = 0; i < 4; ++i)
            out[b0 + ty * 4 + i] += wkv * kan[i];
    }
}

extern "C" void kernel_launch(void* const* d_in, const int* in_sizes, int n_in,
                              void* d_out, int out_size) {
    const float* x_kan   = (const float*)d_in[0];
    const float* x_mamba = (const float*)d_in[1];
    const float* in_w1 = (const float*)d_in[2];
    const float* in_b1 = (const float*)d_in[3];
    const float* in_w2 = (const float*)d_in[4];
    const float* in_b2 = (const float*)d_in[5];
    const float* in_ww = (const float*)d_in[6];
    const float* in_bw = (const float*)d_in[7];
    const float* in_wb = (const float*)d_in[8];
    const float* in_bb = (const float*)d_in[9];
    const float* out_w1 = (const float*)d_in[10];
    const float* out_b1 = (const float*)d_in[11];
    const float* out_w2 = (const float*)d_in[12];
    const float* out_b2 = (const float*)d_in[13];
    const float* out_ww = (const float*)d_in[14];
    const float* out_bw = (const float*)d_in[15];
    const float* out_wb = (const float*)d_in[16];
    const float* out_bb = (const float*)d_in[17];
    const float* A      = (const float*)d_in[18];
    const float* B_ssm  = (const float*)d_in[19];
    const float* C_ssm  = (const float*)d_in[20];
    const float* wk     = (const float*)d_in[21];
    const float* wm     = (const float*)d_in[22];
    float* out = (float*)d_out;

    const int MGSMEM = (256 * 34 + 256 * 36) * 4;                       // 71680 (prelude max)
    const int S2SMEM = (3 * 64 * 68 + 64 + 64) * 4;                     // 52736
    cudaFuncSetAttribute(mega_kernel, cudaFuncAttributeMaxDynamicSharedMemorySize, MGSMEM);
    cudaFuncSetAttribute(stage2_kernel, cudaFuncAttributeMaxDynamicSharedMemorySize, S2SMEM);

    ksums_kernel<<<130, 32>>>(in_wb, in_bb);                          // 1 (+ctr/flag reset)
    mega_kernel<<<64 + 256 + 2048 + 512, 256, MGSMEM>>>(x_kan, in_w1, in_b1,
                                                        x_mamba, wm,
                                                        A, B_ssm, C_ssm,
                                                        in_w2, in_b2, out); // 2
    stage2_kernel<<<dim3(2, Bn / 64), 256, S2SMEM>>>(x_kan, in_ww, in_bw);  // 3
    outer_kernel<<<Bn / 64, 256>>>(out_w1, out_b1, out_w2, out_b2,
                                   out_ww, out_bw, out_wb, out_bb, wk, out); // 4 (profiled)
}

// round 14
// speedup vs baseline: 1.7723x; 1.0409x over previous
#include <cuda_runtime.h>
#include <math.h>
#include <cstdint>

#define Bn    16384
#define KINd  1024
#define MINd  64
#define Sd    256
#define Td    128
#define H1d   128
#define H2d   64

typedef unsigned long long ull;

// ------------------------- scratch (device globals; no allocs) --------------
static __device__ __align__(16) float g_Pw[6 * Sd * Sd];   // A^2,4,8,16,32,64
static __device__ __align__(16) float g_ST[128 * Sd];      // S^T: row n = A^n c
static __device__ __align__(16) float g_M[Td * MINd];
static __device__ __align__(16) float g_h1[(size_t)Bn * 2 * H1d];   // 16 MB
static __device__ __align__(16) float g_h2[(size_t)Bn * 2 * H2d];   // 8 MB
static __device__ __align__(16) float g_inner[(size_t)Bn * 2];
static __device__ float g_sWb[2 * H2d];
static __device__ float g_sbb[2];
static __device__ volatile int g_sync[16];     // [15] = M-ready counter
static __device__ volatile int g_tdone[256];   // gemm1 tile-done flags
static __device__ volatile int g_t2done[512];  // gemm2 tile-done flags

// ---- FMA-only softplus (no MUFU) -------------------------------------------
__device__ __forceinline__ float sp_poly(float s) {
    float t = fmaxf(-fabsf(s), -17.f);
    float z = t * 1.44269504f;
    int   ni = __float2int_rn(z);
    float f = z - (float)ni;
    float p = 1.33335581e-3f;
    p = fmaf(p, f, 9.61812911e-3f);
    p = fmaf(p, f, 5.55041087e-2f);
    p = fmaf(p, f, 2.40226507e-1f);
    p = fmaf(p, f, 6.93147181e-1f);
    p = fmaf(p, f, 1.f);
    float y = __int_as_float((ni + 127) << 23) * p;
    float v = 2.f + y;
    float r0 = fmaf(-0.1716f, v, 0.8249f);
    r0 = r0 * fmaf(-v, r0, 2.f);
    r0 = r0 * fmaf(-v, r0, 2.f);
    float r  = y * r0;
    float r2 = r * r;
    float q = fmaf(r2, 0.28571429f, 0.4f);
    q = fmaf(r2, q, 0.66666667f);
    q = fmaf(r2, q, 2.f);
    return fmaxf(s, 0.f) + r * q;
}

// ---- packed f32x2 helpers ---------------------------------------------------
__device__ __forceinline__ void ffma2(ull& d, ull a, ull b) {
    asm("fma.rn.f32x2 %0, %1, %2, %0;" : "+l"(d) : "l"(a), "l"(b));
}
__device__ __forceinline__ ull pack2(float lo, float hi) {
    ull r; asm("mov.b64 %0, {%1, %2};" : "=l"(r) : "f"(lo), "f"(hi)); return r;
}
__device__ __forceinline__ void unpack2(ull v, float& lo, float& hi) {
    asm("mov.b64 {%0, %1}, %2;" : "=f"(lo), "=f"(hi) : "l"(v));
}

// ---- resident-grid sync among prelude blocks (counters reset by ksums) ------
__device__ __forceinline__ void grid_sync(int s, int n) {
    __threadfence();
    __syncthreads();
    if (threadIdx.x == 0) {
        atomicAdd((int*)&g_sync[s], 1);
        while (*(volatile int*)&g_sync[s] < n) { }
        __threadfence();
    }
    __syncthreads();
}

// row-sums of in_wb / in_bb (bias-collapse) + counter/flag reset for replays
__global__ void ksums_kernel(const float* __restrict__ wb,
                             const float* __restrict__ bb) {
    int r = blockIdx.x, lane = threadIdx.x;
    if (r == 0) {
        if (lane == 0)
#pragma unroll
            for (int s = 0; s < 16; ++s) g_sync[s] = 0;
        for (int i = lane; i < 256; i += 32) g_tdone[i] = 0;
        for (int i = lane; i < 512; i += 32) g_t2done[i] = 0;
    }
    float s = 0.f;
    if (r < 128) {
        const float* row = wb + (size_t)r * KINd;
        for (int i = lane; i < KINd; i += 32) s += row[i];
    } else if (r < 130) {
        const float* row = bb + (size_t)(r - 128) * KINd;
        for (int i = lane; i < KINd; i += 32) s += row[i];
    }
#pragma unroll
    for (int o = 16; o > 0; o >>= 1) s += __shfl_down_sync(0xffffffffu, s, o);
    if (lane == 0) {
        if (r < 128) g_sWb[r] = s;
        else if (r < 130) g_sbb[r - 128] = s;
    }
}

// ---------- MEGA kernel ------------------------------------------------------
// blocks 0..63     : SSM prelude (A powers -> Krylov doubling -> M)
// blocks 64..319   : gemm1  (sets g_tdone)
// blocks 320..2367 : mamba  (waits on M-ready)
// blocks 2368..2879: gemm2  (waits g_tdone, sets g_t2done)
// blocks 2880..3391: stage2 (waits g_t2done)
__global__ void __launch_bounds__(256) mega_kernel(const float* __restrict__ x,
                                                   const float* __restrict__ w1,
                                                   const float* __restrict__ b1,
                                                   const float* __restrict__ xm,
                                                   const float* __restrict__ wm,
                                                   const float* __restrict__ A,
                                                   const float* __restrict__ Bssm,
                                                   const float* __restrict__ Cssm,
                                                   const float* __restrict__ w2,
                                                   const float* __restrict__ b2,
                                                   const float* __restrict__ ww,
                                                   const float* __restrict__ bw,
                                                   float* __restrict__ out) {
    extern __shared__ char dynsm[];
    const int vb = blockIdx.x;
    const int t = threadIdx.x;

    if (vb < 64) {
        // ================= prelude =================
        float* As = (float*)dynsm;            // [256][34] transposed L tile
        float* Bs = (float*)dynsm + 256 * 34; // [256][36] R tile
        const int tx = t & 15, ty = t >> 4;
        const int rb = (vb >> 3) * 32, cb = (vb & 7) * 32;
        const int warp = t >> 5, lane = t & 31;
        const int wgid = vb * 8 + warp;       // 0..511

        if (vb == 0) g_ST[t] = Cssm[t];       // S^T row 0 = c

#pragma unroll
        for (int s = 0; s < 6; ++s) {
            const float* L = (s == 0) ? A : g_Pw + (size_t)(s - 1) * Sd * Sd;
            float* C = g_Pw + (size_t)s * Sd * Sd;
            for (int q = t; q < 2048; q += 256) {
                int i = q >> 6, k4 = (q & 63) * 4;
                float4 v = *(const float4*)(L + (size_t)(rb + i) * Sd + k4);
                As[(k4 + 0) * 34 + i] = v.x;
                As[(k4 + 1) * 34 + i] = v.y;
                As[(k4 + 2) * 34 + i] = v.z;
                As[(k4 + 3) * 34 + i] = v.w;
            }
            for (int q = t; q < 2048; q += 256) {
                int k = q >> 3, j4 = (q & 7) * 4;
                *(float4*)&Bs[k * 36 + j4] = *(const float4*)(L + (size_t)k * Sd + cb + j4);
            }
            __syncthreads();
            float c00 = 0.f, c01 = 0.f, c10 = 0.f, c11 = 0.f;
#pragma unroll 8
            for (int k = 0; k < 256; ++k) {
                float2 av = *(float2*)&As[k * 34 + ty * 2];
                float2 bv = *(float2*)&Bs[k * 36 + tx * 2];
                c00 += av.x * bv.x; c01 += av.x * bv.y;
                c10 += av.y * bv.x; c11 += av.y * bv.y;
            }
            C[(size_t)(rb + ty * 2) * Sd + cb + tx * 2]         = c00;
            C[(size_t)(rb + ty * 2) * Sd + cb + tx * 2 + 1]     = c01;
            C[(size_t)(rb + ty * 2 + 1) * Sd + cb + tx * 2]     = c10;
            C[(size_t)(rb + ty * 2 + 1) * Sd + cb + tx * 2 + 1] = c11;
            if (s < 5) grid_sync(s, 64);
        }

        int width = 1;
#pragma unroll
        for (int k = 0; k < 7; ++k) {
            const float* Pb = (k == 0) ? A : g_Pw + (size_t)(k - 1) * Sd * Sd;
            const int nout = Sd * width;
            for (int e = wgid; e < nout; e += 512) {
                const int cc = e >> 8, i = e & 255;
                const float4* p4 = (const float4*)(Pb + (size_t)i * Sd);
                const float4* s4 = (const float4*)(g_ST + cc * Sd);
                float4 a0 = p4[2 * lane], a1 = p4[2 * lane + 1];
                float4 s0 = s4[2 * lane], s1 = s4[2 * lane + 1];
                float acc = a0.x * s0.x + a0.y * s0.y + a0.z * s0.z + a0.w * s0.w
                          + a1.x * s1.x + a1.y * s1.y + a1.z * s1.z + a1.w * s1.w;
#pragma unroll
                for (int o = 16; o > 0; o >>= 1)
                    acc += __shfl_down_sync(0xffffffffu, acc, o);
                if (lane == 0) g_ST[(width + cc) * Sd + i] = acc;
            }
            grid_sync(5 + k, 64);
            width <<= 1;
        }

        for (int e = wgid; e < Td * MINd; e += 512) {
            const int tau = e >> 6, m = e & 63;
            const float4* b4 = (const float4*)(Bssm + (size_t)m * Sd);
            const float4* s4 = (const float4*)(g_ST + (127 - tau) * Sd);
            float4 a0 = b4[2 * lane], a1 = b4[2 * lane + 1];
            float4 s0 = s4[2 * lane], s1 = s4[2 * lane + 1];
            float acc = a0.x * s0.x + a0.y * s0.y + a0.z * s0.z + a0.w * s0.w
                      + a1.x * s1.x + a1.y * s1.y + a1.z * s1.z + a1.w * s1.w;
#pragma unroll
            for (int o = 16; o > 0; o >>= 1)
                acc += __shfl_down_sync(0xffffffffu, acc, o);
            if (lane == 0) g_M[tau * MINd + m] = acc;
        }
        __threadfence();
        __syncthreads();
        if (t == 0) atomicAdd((int*)&g_sync[15], 1);   // release M
    } else if (vb < 320) {
        // ================= gemm1 (f32x2 SIMT, 128x128 tile) =================
        float* xs = (float*)dynsm;               // [128][36]
        float* ws = (float*)dynsm + 128 * 36;    // [32][128]
        const int vg = vb - 64;
        const int u = vg & 1;
        const int b0 = (vg >> 1) * 128;
        const int tx = t & 15;
        const int ty = t >> 4;
        const float* w1u = w1 + (size_t)u * KINd * H1d;
        const float* b1u = b1 + (size_t)u * H1d;

        ull acc2[8][4];
#pragma unroll
        for (int r = 0; r < 8; ++r)
#pragma unroll
            for (int j = 0; j < 4; ++j) acc2[r][j] = 0ULL;

        for (int k0 = 0; k0 < KINd; k0 += 32) {
            for (int q = t; q < 1024; q += 256) {
                int r = q >> 3, c = q & 7;
                *(float4*)&xs[r * 36 + c * 4] =
                    *(const float4*)(x + (size_t)(b0 + r) * KINd + k0 + c * 4);
            }
            for (int q = t; q < 1024; q += 256) {
                int r = q >> 5, c = q & 31;
                *(float4*)&ws[r * 128 + c * 4] =
                    *(const float4*)(w1u + (size_t)(k0 + r) * H1d + c * 4);
            }
            __syncthreads();
#pragma unroll 4
            for (int kk = 0; kk < 32; ++kk) {
                ull ap[8];
#pragma unroll
                for (int r = 0; r < 8; ++r) {
                    float a = xs[(ty * 8 + r) * 36 + kk];
                    ap[r] = pack2(a, a);
                }
                ulonglong2 wa = *(const ulonglong2*)&ws[kk * 128 + tx * 8];
                ulonglong2 wb = *(const ulonglong2*)&ws[kk * 128 + tx * 8 + 4];
#pragma unroll
                for (int r = 0; r < 8; ++r) {
                    ffma2(acc2[r][0], ap[r], wa.x);
                    ffma2(acc2[r][1], ap[r], wa.y);
                    ffma2(acc2[r][2], ap[r], wb.x);
                    ffma2(acc2[r][3], ap[r], wb.y);
                }
            }
            __syncthreads();
        }
#pragma unroll
        for (int r = 0; r < 8; ++r) {
            int b = b0 + ty * 8 + r;
            float* dst = g_h1 + ((size_t)b * 2 + u) * H1d + tx * 8;
#pragma unroll
            for (int j = 0; j < 4; ++j) {
                float lo, hi;
                unpack2(acc2[r][j], lo, hi);
                int n = tx * 8 + 2 * j;
                float v0 = fmaxf(lo + b1u[n], 0.f);
                float v1 = fmaxf(hi + b1u[n + 1], 0.f);
                float2 o2; o2.x = v0; o2.y = v1;
                *(float2*)(dst + 2 * j) = o2;
            }
        }
        __threadfence();
        __syncthreads();
        if (t == 0) g_tdone[vg] = 1;               // release this h1 tile
    } else if (vb < 2368) {
        // ================= mamba: 8 warps, one row each =================
        if (t == 0) {
            while (*(volatile int*)&g_sync[15] < 64) { }
            __threadfence();
        }
        __syncthreads();
        float4* Ms = (float4*)dynsm;     // 2048 float4 = 32 KB
        const float4* Mg = (const float4*)g_M;
        for (int q = t; q < 2048; q += 256) Ms[q] = __ldcg(Mg + q);
        __syncthreads();
        const int warp = t >> 5, lane = t & 31;
        const int b = (vb - 320) * 8 + warp;
        const float4* xr = (const float4*)(xm + (size_t)b * (Td * MINd));
        float acc = 0.f;
#pragma unroll 8
        for (int j = lane; j < 2048; j += 32) {
            float4 xv = xr[j];
            float4 mv = Ms[j];
            acc += xv.x * mv.x + xv.y * mv.y + xv.z * mv.z + xv.w * mv.w;
        }
#pragma unroll
        for (int o = 16; o > 0; o >>= 1) acc += __shfl_down_sync(0xffffffffu, acc, o);
        if (lane == 0) out[b] = wm[0] * acc;
    } else if (vb < 2880) {
        // ================= gemm2: waits on its h1 producer tile =============
        float* hs  = (float*)dynsm;              // [64][65]
        float* w2s = (float*)dynsm + 64 * 65;    // [64][64]
        const int vg2 = vb - 2368;
        const int u = vg2 & 1;
        const int b0 = (vg2 >> 1) * 64;
        const int flag = ((b0 >> 7) << 1) | u;   // producer gemm1 vg
        if (t == 0) {
            while (*(volatile int*)&g_tdone[flag] == 0) { }
            __threadfence();
        }
        __syncthreads();

        const int tx = t & 15;
        const int ty = t >> 4;
        const float* w2u = w2 + (size_t)u * H1d * H2d;

        float acc[4][4];
#pragma unroll
        for (int i = 0; i < 4; ++i)
#pragma unroll
            for (int j = 0; j < 4; ++j) acc[i][j] = 0.f;

        for (int k0 = 0; k0 < H1d; k0 += 64) {
            for (int q = t; q < 1024; q += 256) {
                int r = q >> 4, c = q & 15;
                float4 v = *(const float4*)(g_h1 + ((size_t)(b0 + r) * 2 + u) * H1d + k0 + c * 4);
                hs[r * 65 + c * 4 + 0] = v.x; hs[r * 65 + c * 4 + 1] = v.y;
                hs[r * 65 + c * 4 + 2] = v.z; hs[r * 65 + c * 4 + 3] = v.w;
            }
            for (int q = t; q < 1024; q += 256) {
                int r = q >> 4, c = q & 15;
                *(float4*)&w2s[r * 64 + c * 4] = *(const float4*)(w2u + (size_t)(k0 + r) * H2d + c * 4);
            }
            __syncthreads();
#pragma unroll 8
            for (int f = 0; f < 64; ++f) {
                float4 w = *(float4*)&w2s[f * 64 + tx * 4];
                float a0 = hs[(ty * 4 + 0) * 65 + f];
                float a1 = hs[(ty * 4 + 1) * 65 + f];
                float a2 = hs[(ty * 4 + 2) * 65 + f];
                float a3 = hs[(ty * 4 + 3) * 65 + f];
                acc[0][0] += a0 * w.x; acc[0][1] += a0 * w.y; acc[0][2] += a0 * w.z; acc[0][3] += a0 * w.w;
                acc[1][0] += a1 * w.x; acc[1][1] += a1 * w.y; acc[1][2] += a1 * w.z; acc[1][3] += a1 * w.w;
                acc[2][0] += a2 * w.x; acc[2][1] += a2 * w.y; acc[2][2] += a2 * w.z; acc[2][3] += a2 * w.w;
                acc[3][0] += a3 * w.x; acc[3][1] += a3 * w.y; acc[3][2] += a3 * w.z; acc[3][3] += a3 * w.w;
            }
            __syncthreads();
        }
#pragma unroll
        for (int i = 0; i < 4; ++i) {
            int b = b0 + ty * 4 + i;
#pragma unroll
            for (int j = 0; j < 4; ++j) {
                int g = tx * 4 + j;
                float v = acc[i][j] + b2[u * H2d + g];
                g_h2[((size_t)b * 2 + u) * H2d + g] = fmaxf(v, 0.f);
            }
        }
        __threadfence();
        __syncthreads();
        if (t == 0) g_t2done[vg2] = 1;             // release this h2 tile
    } else {
        // ================= stage2: waits on its h2 producer tile ============
        float* h2tf = (float*)dynsm;           // [64 g][68 rows]
        float* wws  = h2tf + 64 * 68;          // [64 g][68 i]
        float* xsh  = wws + 64 * 68;           // [64 rows][68 i]
        float* bws  = xsh + 64 * 68;           // [64]
        float* sWbs = bws + 64;                // [64]
        const int vg3 = vb - 2880;
        const int u = vg3 & 1;
        const int b0 = (vg3 >> 1) * 64;
        if (t == 0) {
            while (*(volatile int*)&g_t2done[vg3] == 0) { }
            __threadfence();
        }
        __syncthreads();

        const int tx = t & 15;
        const int ty = t >> 4;
        const float* wwu = ww + (size_t)u * H2d * KINd;
        const float* bwu = bw + (size_t)u * KINd;

        if (t < 64) sWbs[t] = g_sWb[u * H2d + t];
        for (int q = t; q < 1024; q += 256) {
            int r = q & 63, gq = (q >> 6) * 4;
            float4 v = *(const float4*)(g_h2 + ((size_t)(b0 + r) * 2 + u) * H2d + gq);
            h2tf[(gq + 0) * 68 + r] = v.x;
            h2tf[(gq + 1) * 68 + r] = v.y;
            h2tf[(gq + 2) * 68 + r] = v.z;
            h2tf[(gq + 3) * 68 + r] = v.w;
        }
        __syncthreads();

        ull acc2[2][4];
        float part[4] = {0.f, 0.f, 0.f, 0.f};

        for (int it = 0; it < 16; ++it) {
            int i0 = it * 64;
            __syncthreads();
            for (int q = t; q < 1024; q += 256) {
                int r = q >> 4, c = q & 15;
                *(float4*)&wws[r * 68 + c * 4] =
                    *(const float4*)(wwu + (size_t)r * KINd + i0 + c * 4);
            }
            for (int q = t; q < 1024; q += 256) {
                int r = q >> 4, c = q & 15;
                *(float4*)&xsh[r * 68 + c * 4] =
                    *(const float4*)(x + (size_t)(b0 + r) * KINd + i0 + c * 4);
            }
            if (t < 16) *(float4*)&bws[t * 4] = *(const float4*)(bwu + i0 + t * 4);
            __syncthreads();

#pragma unroll
            for (int rp = 0; rp < 2; ++rp)
#pragma unroll
                for (int j = 0; j < 4; ++j) acc2[rp][j] = 0ULL;

#pragma unroll 8
            for (int g = 0; g < 64; ++g) {
                ulonglong2 ha = *(const ulonglong2*)(h2tf + g * 68 + ty * 4);
                float4 wv = *(const float4*)&wws[g * 68 + tx * 4];
                ull w0 = pack2(wv.x, wv.x), w1p = pack2(wv.y, wv.y);
                ull w2p = pack2(wv.z, wv.z), w3p = pack2(wv.w, wv.w);
                ffma2(acc2[0][0], ha.x, w0); ffma2(acc2[0][1], ha.x, w1p);
                ffma2(acc2[0][2], ha.x, w2p); ffma2(acc2[0][3], ha.x, w3p);
                ffma2(acc2[1][0], ha.y, w0); ffma2(acc2[1][1], ha.y, w1p);
                ffma2(acc2[1][2], ha.y, w2p); ffma2(acc2[1][3], ha.y, w3p);
            }

#pragma unroll
            for (int j = 0; j < 4; ++j) {
                float bwv = bws[tx * 4 + j];
#pragma unroll
                for (int rp = 0; rp < 2; ++rp) {
                    float s0, s1;
                    unpack2(acc2[rp][j], s0, s1);
                    float p0 = sp_poly(s0 + bwv);
                    float p1 = sp_poly(s1 + bwv);
                    part[2 * rp]     += p0 * xsh[(ty * 4 + 2 * rp) * 68 + tx * 4 + j];
                    part[2 * rp + 1] += p1 * xsh[(ty * 4 + 2 * rp + 1) * 68 + tx * 4 + j];
                }
            }
        }

#pragma unroll
        for (int gg = 0; gg < 4; ++gg) {
            int g = tx * 4 + gg;
            float swv = sWbs[g];
#pragma unroll
            for (int r = 0; r < 4; ++r)
                part[r] += h2tf[g * 68 + ty * 4 + r] * swv;
        }
#pragma unroll
        for (int r = 0; r < 4; ++r)
#pragma unroll
            for (int o = 8; o > 0; o >>= 1)
                part[r] += __shfl_down_sync(0xffffffffu, part[r], o, 16);
        if (tx == 0) {
            float sbbv = g_sbb[u];
#pragma unroll
            for (int r = 0; r < 4; ++r)
                g_inner[(size_t)(b0 + ty * 4 + r) * 2 + u] = part[r] + sbbv;
        }
    }
}

// outer MLP as a tiled batched GEMM: 64 b-rows per block, v-loop inside.
__global__ void __launch_bounds__(256) outer_kernel(const float* __restrict__ ow1,
                                                    const float* __restrict__ ob1,
                                                    const float* __restrict__ ow2,
                                                    const float* __restrict__ ob2,
                                                    const float* __restrict__ oww,
                                                    const float* __restrict__ obw,
                                                    const float* __restrict__ owb,
                                                    const float* __restrict__ obb,
                                                    const float* __restrict__ wk,
                                                    float* __restrict__ out) {
    __shared__ float i0s[64], i1s[64];
    __shared__ float w1af[128], w1bf[128], b1f[128];
    __shared__ float W2s[32 * 68];
    __shared__ float g1s[32 * 68];
    __shared__ float ob2s[64], owws[64], owbs[64];
    const int t = threadIdx.x;
    const int tx = t & 15;
    const int ty = t >> 4;
    const int b0 = blockIdx.x * 64;

    if (t < 64) {
        float2 iv = *(const float2*)(g_inner + (size_t)(b0 + t) * 2);
        i0s[t] = iv.x;
        i1s[t] = iv.y;
    }

    float kan[4] = {0.f, 0.f, 0.f, 0.f};

#pragma unroll
    for (int v = 0; v < 2; ++v) {
        __syncthreads();
        if (t < 128) {
            w1af[t] = ow1[(v * 2 + 0) * H1d + t];
            w1bf[t] = ow1[(v * 2 + 1) * H1d + t];
            b1f[t]  = ob1[v * H1d + t];
        } else if (t < 192) {
            int j = t - 128;
            ob2s[j] = ob2[v * H2d + j];
            owws[j] = oww[v * H2d + j];
            owbs[j] = owb[v * H2d + j];
        }
        __syncthreads();

        float acc[4][4];
#pragma unroll
        for (int i = 0; i < 4; ++i)
#pragma unroll
            for (int j = 0; j < 4; ++j) acc[i][j] = 0.f;

        for (int fc = 0; fc < 4; ++fc) {
            const int f0 = fc * 32;
            __syncthreads();
            for (int q = t; q < 2048; q += 256) {
                int f = q >> 6, b = q & 63;
                g1s[f * 68 + b] =
                    fmaxf(fmaf(i0s[b], w1af[f0 + f],
                          fmaf(i1s[b], w1bf[f0 + f], b1f[f0 + f])), 0.f);
            }
            for (int q = t; q < 512; q += 256) {
                int f = q >> 4, c = q & 15;
                *(float4*)&W2s[f * 68 + c * 4] =
                    *(const float4*)(ow2 + ((size_t)v * H1d + f0 + f) * H2d + c * 4);
            }
            __syncthreads();
#pragma unroll 8
            for (int f = 0; f < 32; ++f) {
                float4 w = *(float4*)&W2s[f * 68 + tx * 4];
                float a0 = g1s[f * 68 + ty * 4 + 0];
                float a1 = g1s[f * 68 + ty * 4 + 1];
                float a2 = g1s[f * 68 + ty * 4 + 2];
                float a3 = g1s[f * 68 + ty * 4 + 3];
                acc[0][0] += a0 * w.x; acc[0][1] += a0 * w.y; acc[0][2] += a0 * w.z; acc[0][3] += a0 * w.w;
                acc[1][0] += a1 * w.x; acc[1][1] += a1 * w.y; acc[1][2] += a1 * w.z; acc[1][3] += a1 * w.w;
                acc[2][0] += a2 * w.x; acc[2][1] += a2 * w.y; acc[2][2] += a2 * w.z; acc[2][3] += a2 * w.w;
                acc[3][0] += a3 * w.x; acc[3][1] += a3 * w.y; acc[3][2] += a3 * w.z; acc[3][3] += a3 * w.w;
            }
        }

        float swp[4], sbp[4];
#pragma unroll
        for (int i = 0; i < 4; ++i) { swp[i] = 0.f; sbp[i] = 0.f; }
#pragma unroll
        for (int j = 0; j < 4; ++j) {
            int jj = tx * 4 + j;
            float bz = ob2s[jj], wwv = owws[jj], wbv = owbs[jj];
#pragma unroll
            for (int i = 0; i < 4; ++i) {
                float g2 = fmaxf(acc[i][j] + bz, 0.f);
                swp[i] += g2 * wwv;
                sbp[i] += g2 * wbv;
            }
        }
#pragma unroll
        for (int i = 0; i < 4; ++i) {
#pragma unroll
            for (int o = 8; o > 0; o >>= 1) {
                swp[i] += __shfl_down_sync(0xffffffffu, swp[i], o, 16);
                sbp[i] += __shfl_down_sync(0xffffffffu, sbp[i], o, 16);
            }
        }
        if (tx == 0) {
            float obwv = obw[v], obbv = obb[v];
#pragma unroll
            for (int i = 0; i < 4; ++i) {
                int b = ty * 4 + i;
                float wout = sp_poly(swp[i] + obwv);
                kan[i] += wout * (i0s[b] + i1s[b]) + 2.f * (sbp[i] + obbv);
            }
        }
    }

    if (tx == 0) {
        float wkv = wk[0];
#pragma unroll
        for (int i = 0; i < 4; ++i)
            out[b0 + ty * 4 + i] += wkv * kan[i];
    }
}

extern "C" void kernel_launch(void* const* d_in, const int* in_sizes, int n_in,
                              void* d_out, int out_size) {
    const float* x_kan   = (const float*)d_in[0];
    const float* x_mamba = (const float*)d_in[1];
    const float* in_w1 = (const float*)d_in[2];
    const float* in_b1 = (const float*)d_in[3];
    const float* in_w2 = (const float*)d_in[4];
    const float* in_b2 = (const float*)d_in[5];
    const float* in_ww = (const float*)d_in[6];
    const float* in_bw = (const float*)d_in[7];
    const float* in_wb = (const float*)d_in[8];
    const float* in_bb = (const float*)d_in[9];
    const float* out_w1 = (const float*)d_in[10];
    const float* out_b1 = (const float*)d_in[11];
    const float* out_w2 = (const float*)d_in[12];
    const float* out_b2 = (const float*)d_in[13];
    const float* out_ww = (const float*)d_in[14];
    const float* out_bw = (const float*)d_in[15];
    const float* out_wb = (const float*)d_in[16];
    const float* out_bb = (const float*)d_in[17];
    const float* A      = (const float*)d_in[18];
    const float* B_ssm  = (const float*)d_in[19];
    const float* C_ssm  = (const float*)d_in[20];
    const float* wk     = (const float*)d_in[21];
    const float* wm     = (const float*)d_in[22];
    float* out = (float*)d_out;

    const int MGSMEM = (256 * 34 + 256 * 36) * 4;   // 71680 (prelude max)
    cudaFuncSetAttribute(mega_kernel, cudaFuncAttributeMaxDynamicSharedMemorySize, MGSMEM);

    ksums_kernel<<<130, 32>>>(in_wb, in_bb);                          // 1 (+ctr/flag reset)
    mega_kernel<<<64 + 256 + 2048 + 512 + 512, 256, MGSMEM>>>(
        x_kan, in_w1, in_b1, x_mamba, wm, A, B_ssm, C_ssm,
        in_w2, in_b2, in_ww, in_bw, out);                             // 2
    outer_kernel<<<Bn / 64, 256>>>(out_w1, out_b1, out_w2, out_b2,
                                   out_ww, out_bw, out_wb, out_bb, wk, out); // 3
}

// round 15
// speedup vs baseline: 1.7768x; 1.0025x over previous
#include <cuda_runtime.h>
#include <math.h>
#include <cstdint>

#define Bn    16384
#define KINd  1024
#define MINd  64
#define Sd    256
#define Td    128
#define H1d   128
#define H2d   64

typedef unsigned long long ull;

// ------------------------- scratch (device globals; no allocs) --------------
static __device__ __align__(16) float g_Pw[6 * Sd * Sd];   // A^2,4,8,16,32,64
static __device__ __align__(16) float g_ST[128 * Sd];      // S^T: row n = A^n c
static __device__ __align__(16) float g_M[Td * MINd];
static __device__ __align__(16) float g_h1[(size_t)Bn * 2 * H1d];   // 16 MB
static __device__ __align__(16) float g_h2[(size_t)Bn * 2 * H2d];   // 8 MB
static __device__ __align__(16) float g_inner[(size_t)Bn * 2];
static __device__ float g_sWb[2 * H2d];
static __device__ float g_sbb[2];
static __device__ volatile int g_sync[16];     // [15] = M-ready counter
static __device__ volatile int g_tdone[256];   // gemm1 tile-done flags
static __device__ volatile int g_t2done[512];  // gemm2 tile-done flags
static __device__ volatile int g_t3done[512];  // stage2 tile-done flags
static __device__ volatile int g_mcnt[256];    // mamba 64-row-group counters

// ---- FMA-only softplus (no MUFU) -------------------------------------------
__device__ __forceinline__ float sp_poly(float s) {
    float t = fmaxf(-fabsf(s), -17.f);
    float z = t * 1.44269504f;
    int   ni = __float2int_rn(z);
    float f = z - (float)ni;
    float p = 1.33335581e-3f;
    p = fmaf(p, f, 9.61812911e-3f);
    p = fmaf(p, f, 5.55041087e-2f);
    p = fmaf(p, f, 2.40226507e-1f);
    p = fmaf(p, f, 6.93147181e-1f);
    p = fmaf(p, f, 1.f);
    float y = __int_as_float((ni + 127) << 23) * p;
    float v = 2.f + y;
    float r0 = fmaf(-0.1716f, v, 0.8249f);
    r0 = r0 * fmaf(-v, r0, 2.f);
    r0 = r0 * fmaf(-v, r0, 2.f);
    float r  = y * r0;
    float r2 = r * r;
    float q = fmaf(r2, 0.28571429f, 0.4f);
    q = fmaf(r2, q, 0.66666667f);
    q = fmaf(r2, q, 2.f);
    return fmaxf(s, 0.f) + r * q;
}

// ---- packed f32x2 helpers ---------------------------------------------------
__device__ __forceinline__ void ffma2(ull& d, ull a, ull b) {
    asm("fma.rn.f32x2 %0, %1, %2, %0;" : "+l"(d) : "l"(a), "l"(b));
}
__device__ __forceinline__ ull pack2(float lo, float hi) {
    ull r; asm("mov.b64 %0, {%1, %2};" : "=l"(r) : "f"(lo), "f"(hi)); return r;
}
__device__ __forceinline__ void unpack2(ull v, float& lo, float& hi) {
    asm("mov.b64 {%0, %1}, %2;" : "=f"(lo), "=f"(hi) : "l"(v));
}

// ---- resident-grid sync among prelude blocks (counters reset by ksums) ------
__device__ __forceinline__ void grid_sync(int s, int n) {
    __threadfence();
    __syncthreads();
    if (threadIdx.x == 0) {
        atomicAdd((int*)&g_sync[s], 1);
        while (*(volatile int*)&g_sync[s] < n) { }
        __threadfence();
    }
    __syncthreads();
}

// row-sums of in_wb / in_bb (bias-collapse) + counter/flag reset for replays
__global__ void ksums_kernel(const float* __restrict__ wb,
                             const float* __restrict__ bb) {
    int r = blockIdx.x, lane = threadIdx.x;
    if (r == 0) {
        if (lane == 0)
#pragma unroll
            for (int s = 0; s < 16; ++s) g_sync[s] = 0;
        for (int i = lane; i < 256; i += 32) { g_tdone[i] = 0; g_mcnt[i] = 0; }
        for (int i = lane; i < 512; i += 32) { g_t2done[i] = 0; g_t3done[i] = 0; }
    }
    float s = 0.f;
    if (r < 128) {
        const float* row = wb + (size_t)r * KINd;
        for (int i = lane; i < KINd; i += 32) s += row[i];
    } else if (r < 130) {
        const float* row = bb + (size_t)(r - 128) * KINd;
        for (int i = lane; i < KINd; i += 32) s += row[i];
    }
#pragma unroll
    for (int o = 16; o > 0; o >>= 1) s += __shfl_down_sync(0xffffffffu, s, o);
    if (lane == 0) {
        if (r < 128) g_sWb[r] = s;
        else if (r < 130) g_sbb[r - 128] = s;
    }
}

// ---------- MEGA kernel ------------------------------------------------------
// blocks 0..63     : SSM prelude (A powers -> Krylov doubling -> M)
// blocks 64..319   : gemm1  (sets g_tdone)
// blocks 320..2367 : mamba  (waits on M-ready; bumps g_mcnt)
// blocks 2368..2879: gemm2  (waits g_tdone, sets g_t2done)
// blocks 2880..3391: stage2 (waits g_t2done, sets g_t3done)
// blocks 3392..3647: outer  (waits g_t3done pair + g_mcnt group)
__global__ void __launch_bounds__(256) mega_kernel(const float* __restrict__ x,
                                                   const float* __restrict__ w1,
                                                   const float* __restrict__ b1,
                                                   const float* __restrict__ xm,
                                                   const float* __restrict__ wm,
                                                   const float* __restrict__ A,
                                                   const float* __restrict__ Bssm,
                                                   const float* __restrict__ Cssm,
                                                   const float* __restrict__ w2,
                                                   const float* __restrict__ b2,
                                                   const float* __restrict__ ww,
                                                   const float* __restrict__ bw,
                                                   const float* __restrict__ ow1,
                                                   const float* __restrict__ ob1,
                                                   const float* __restrict__ ow2,
                                                   const float* __restrict__ ob2,
                                                   const float* __restrict__ oww,
                                                   const float* __restrict__ obw,
                                                   const float* __restrict__ owb,
                                                   const float* __restrict__ obb,
                                                   const float* __restrict__ wk,
                                                   float* __restrict__ out) {
    extern __shared__ char dynsm[];
    const int vb = blockIdx.x;
    const int t = threadIdx.x;

    if (vb < 64) {
        // ================= prelude =================
        float* As = (float*)dynsm;            // [256][34]
        float* Bs = (float*)dynsm + 256 * 34; // [256][36]
        const int tx = t & 15, ty = t >> 4;
        const int rb = (vb >> 3) * 32, cb = (vb & 7) * 32;
        const int warp = t >> 5, lane = t & 31;
        const int wgid = vb * 8 + warp;

        if (vb == 0) g_ST[t] = Cssm[t];

#pragma unroll
        for (int s = 0; s < 6; ++s) {
            const float* L = (s == 0) ? A : g_Pw + (size_t)(s - 1) * Sd * Sd;
            float* C = g_Pw + (size_t)s * Sd * Sd;
            for (int q = t; q < 2048; q += 256) {
                int i = q >> 6, k4 = (q & 63) * 4;
                float4 v = *(const float4*)(L + (size_t)(rb + i) * Sd + k4);
                As[(k4 + 0) * 34 + i] = v.x;
                As[(k4 + 1) * 34 + i] = v.y;
                As[(k4 + 2) * 34 + i] = v.z;
                As[(k4 + 3) * 34 + i] = v.w;
            }
            for (int q = t; q < 2048; q += 256) {
                int k = q >> 3, j4 = (q & 7) * 4;
                *(float4*)&Bs[k * 36 + j4] = *(const float4*)(L + (size_t)k * Sd + cb + j4);
            }
            __syncthreads();
            float c00 = 0.f, c01 = 0.f, c10 = 0.f, c11 = 0.f;
#pragma unroll 8
            for (int k = 0; k < 256; ++k) {
                float2 av = *(float2*)&As[k * 34 + ty * 2];
                float2 bv = *(float2*)&Bs[k * 36 + tx * 2];
                c00 += av.x * bv.x; c01 += av.x * bv.y;
                c10 += av.y * bv.x; c11 += av.y * bv.y;
            }
            C[(size_t)(rb + ty * 2) * Sd + cb + tx * 2]         = c00;
            C[(size_t)(rb + ty * 2) * Sd + cb + tx * 2 + 1]     = c01;
            C[(size_t)(rb + ty * 2 + 1) * Sd + cb + tx * 2]     = c10;
            C[(size_t)(rb + ty * 2 + 1) * Sd + cb + tx * 2 + 1] = c11;
            if (s < 5) grid_sync(s, 64);
        }

        int width = 1;
#pragma unroll
        for (int k = 0; k < 7; ++k) {
            const float* Pb = (k == 0) ? A : g_Pw + (size_t)(k - 1) * Sd * Sd;
            const int nout = Sd * width;
            for (int e = wgid; e < nout; e += 512) {
                const int cc = e >> 8, i = e & 255;
                const float4* p4 = (const float4*)(Pb + (size_t)i * Sd);
                const float4* s4 = (const float4*)(g_ST + cc * Sd);
                float4 a0 = p4[2 * lane], a1 = p4[2 * lane + 1];
                float4 s0 = s4[2 * lane], s1 = s4[2 * lane + 1];
                float acc = a0.x * s0.x + a0.y * s0.y + a0.z * s0.z + a0.w * s0.w
                          + a1.x * s1.x + a1.y * s1.y + a1.z * s1.z + a1.w * s1.w;
#pragma unroll
                for (int o = 16; o > 0; o >>= 1)
                    acc += __shfl_down_sync(0xffffffffu, acc, o);
                if (lane == 0) g_ST[(width + cc) * Sd + i] = acc;
            }
            grid_sync(5 + k, 64);
            width <<= 1;
        }

        for (int e = wgid; e < Td * MINd; e += 512) {
            const int tau = e >> 6, m = e & 63;
            const float4* b4 = (const float4*)(Bssm + (size_t)m * Sd);
            const float4* s4 = (const float4*)(g_ST + (127 - tau) * Sd);
            float4 a0 = b4[2 * lane], a1 = b4[2 * lane + 1];
            float4 s0 = s4[2 * lane], s1 = s4[2 * lane + 1];
            float acc = a0.x * s0.x + a0.y * s0.y + a0.z * s0.z + a0.w * s0.w
                      + a1.x * s1.x + a1.y * s1.y + a1.z * s1.z + a1.w * s1.w;
#pragma unroll
            for (int o = 16; o > 0; o >>= 1)
                acc += __shfl_down_sync(0xffffffffu, acc, o);
            if (lane == 0) g_M[tau * MINd + m] = acc;
        }
        __threadfence();
        __syncthreads();
        if (t == 0) atomicAdd((int*)&g_sync[15], 1);   // release M
    } else if (vb < 320) {
        // ================= gemm1 (f32x2 SIMT, transposed x in smem) =========
        float* xsT = (float*)dynsm;              // [32 kk][132 rows]
        float* ws  = (float*)dynsm + 32 * 132;   // [32 kk][128 n]
        const int vg = vb - 64;
        const int u = vg & 1;
        const int b0 = (vg >> 1) * 128;
        const int tx = t & 15;
        const int ty = t >> 4;
        const float* w1u = w1 + (size_t)u * KINd * H1d;
        const float* b1u = b1 + (size_t)u * H1d;

        ull acc2[8][4];
#pragma unroll
        for (int r = 0; r < 8; ++r)
#pragma unroll
            for (int j = 0; j < 4; ++j) acc2[r][j] = 0ULL;

        for (int k0 = 0; k0 < KINd; k0 += 32) {
            for (int q = t; q < 1024; q += 256) {
                int row = q >> 3, c = q & 7;
                float4 v = *(const float4*)(x + (size_t)(b0 + row) * KINd + k0 + c * 4);
                xsT[(c * 4 + 0) * 132 + row] = v.x;
                xsT[(c * 4 + 1) * 132 + row] = v.y;
                xsT[(c * 4 + 2) * 132 + row] = v.z;
                xsT[(c * 4 + 3) * 132 + row] = v.w;
            }
            for (int q = t; q < 1024; q += 256) {
                int r = q >> 5, c = q & 31;
                *(float4*)&ws[r * 128 + c * 4] =
                    *(const float4*)(w1u + (size_t)(k0 + r) * H1d + c * 4);
            }
            __syncthreads();
#pragma unroll 4
            for (int kk = 0; kk < 32; ++kk) {
                float4 xa = *(float4*)&xsT[kk * 132 + ty * 8];
                float4 xb = *(float4*)&xsT[kk * 132 + ty * 8 + 4];
                ull ap[8];
                ap[0] = pack2(xa.x, xa.x); ap[1] = pack2(xa.y, xa.y);
                ap[2] = pack2(xa.z, xa.z); ap[3] = pack2(xa.w, xa.w);
                ap[4] = pack2(xb.x, xb.x); ap[5] = pack2(xb.y, xb.y);
                ap[6] = pack2(xb.z, xb.z); ap[7] = pack2(xb.w, xb.w);
                ulonglong2 wa = *(const ulonglong2*)&ws[kk * 128 + tx * 8];
                ulonglong2 wb = *(const ulonglong2*)&ws[kk * 128 + tx * 8 + 4];
#pragma unroll
                for (int r = 0; r < 8; ++r) {
                    ffma2(acc2[r][0], ap[r], wa.x);
                    ffma2(acc2[r][1], ap[r], wa.y);
                    ffma2(acc2[r][2], ap[r], wb.x);
                    ffma2(acc2[r][3], ap[r], wb.y);
                }
            }
            __syncthreads();
        }
#pragma unroll
        for (int r = 0; r < 8; ++r) {
            int b = b0 + ty * 8 + r;
            float* dst = g_h1 + ((size_t)b * 2 + u) * H1d + tx * 8;
#pragma unroll
            for (int j = 0; j < 4; ++j) {
                float lo, hi;
                unpack2(acc2[r][j], lo, hi);
                int n = tx * 8 + 2 * j;
                float v0 = fmaxf(lo + b1u[n], 0.f);
                float v1 = fmaxf(hi + b1u[n + 1], 0.f);
                float2 o2; o2.x = v0; o2.y = v1;
                *(float2*)(dst + 2 * j) = o2;
            }
        }
        __threadfence();
        __syncthreads();
        if (t == 0) g_tdone[vg] = 1;
    } else if (vb < 2368) {
        // ================= mamba: 8 warps, one row each =================
        if (t == 0) {
            while (*(volatile int*)&g_sync[15] < 64) { }
            __threadfence();
        }
        __syncthreads();
        float4* Ms = (float4*)dynsm;
        const float4* Mg = (const float4*)g_M;
        for (int q = t; q < 2048; q += 256) Ms[q] = __ldcg(Mg + q);
        __syncthreads();
        const int warp = t >> 5, lane = t & 31;
        const int b = (vb - 320) * 8 + warp;
        const float4* xr = (const float4*)(xm + (size_t)b * (Td * MINd));
        float acc = 0.f;
#pragma unroll 8
        for (int j = lane; j < 2048; j += 32) {
            float4 xv = xr[j];
            float4 mv = Ms[j];
            acc += xv.x * mv.x + xv.y * mv.y + xv.z * mv.z + xv.w * mv.w;
        }
#pragma unroll
        for (int o = 16; o > 0; o >>= 1) acc += __shfl_down_sync(0xffffffffu, acc, o);
        if (lane == 0) out[b] = wm[0] * acc;
        __threadfence();
        __syncthreads();
        if (t == 0) atomicAdd((int*)&g_mcnt[(vb - 320) >> 3], 1);
    } else if (vb < 2880) {
        // ================= gemm2 =================
        float* hs  = (float*)dynsm;              // [64][65]
        float* w2s = (float*)dynsm + 64 * 65;    // [64][64]
        const int vg2 = vb - 2368;
        const int u = vg2 & 1;
        const int b0 = (vg2 >> 1) * 64;
        const int flag = ((b0 >> 7) << 1) | u;
        if (t == 0) {
            while (*(volatile int*)&g_tdone[flag] == 0) { }
            __threadfence();
        }
        __syncthreads();

        const int tx = t & 15;
        const int ty = t >> 4;
        const float* w2u = w2 + (size_t)u * H1d * H2d;

        float acc[4][4];
#pragma unroll
        for (int i = 0; i < 4; ++i)
#pragma unroll
            for (int j = 0; j < 4; ++j) acc[i][j] = 0.f;

        for (int k0 = 0; k0 < H1d; k0 += 64) {
            for (int q = t; q < 1024; q += 256) {
                int r = q >> 4, c = q & 15;
                float4 v = *(const float4*)(g_h1 + ((size_t)(b0 + r) * 2 + u) * H1d + k0 + c * 4);
                hs[r * 65 + c * 4 + 0] = v.x; hs[r * 65 + c * 4 + 1] = v.y;
                hs[r * 65 + c * 4 + 2] = v.z; hs[r * 65 + c * 4 + 3] = v.w;
            }
            for (int q = t; q < 1024; q += 256) {
                int r = q >> 4, c = q & 15;
                *(float4*)&w2s[r * 64 + c * 4] = *(const float4*)(w2u + (size_t)(k0 + r) * H2d + c * 4);
            }
            __syncthreads();
#pragma unroll 8
            for (int f = 0; f < 64; ++f) {
                float4 w = *(float4*)&w2s[f * 64 + tx * 4];
                float a0 = hs[(ty * 4 + 0) * 65 + f];
                float a1 = hs[(ty * 4 + 1) * 65 + f];
                float a2 = hs[(ty * 4 + 2) * 65 + f];
                float a3 = hs[(ty * 4 + 3) * 65 + f];
                acc[0][0] += a0 * w.x; acc[0][1] += a0 * w.y; acc[0][2] += a0 * w.z; acc[0][3] += a0 * w.w;
                acc[1][0] += a1 * w.x; acc[1][1] += a1 * w.y; acc[1][2] += a1 * w.z; acc[1][3] += a1 * w.w;
                acc[2][0] += a2 * w.x; acc[2][1] += a2 * w.y; acc[2][2] += a2 * w.z; acc[2][3] += a2 * w.w;
                acc[3][0] += a3 * w.x; acc[3][1] += a3 * w.y; acc[3][2] += a3 * w.z; acc[3][3] += a3 * w.w;
            }
            __syncthreads();
        }
#pragma unroll
        for (int i = 0; i < 4; ++i) {
            int b = b0 + ty * 4 + i;
#pragma unroll
            for (int j = 0; j < 4; ++j) {
                int g = tx * 4 + j;
                float v = acc[i][j] + b2[u * H2d + g];
                g_h2[((size_t)b * 2 + u) * H2d + g] = fmaxf(v, 0.f);
            }
        }
        __threadfence();
        __syncthreads();
        if (t == 0) g_t2done[vg2] = 1;
    } else if (vb < 3392) {
        // ================= stage2 =================
        float* h2tf = (float*)dynsm;           // [64 g][68 rows]
        float* wws  = h2tf + 64 * 68;          // [64 g][68 i]
        float* xsh  = wws + 64 * 68;           // [64 rows][68 i]
        float* bws  = xsh + 64 * 68;           // [64]
        float* sWbs = bws + 64;                // [64]
        const int vg3 = vb - 2880;
        const int u = vg3 & 1;
        const int b0 = (vg3 >> 1) * 64;
        if (t == 0) {
            while (*(volatile int*)&g_t2done[vg3] == 0) { }
            __threadfence();
        }
        __syncthreads();

        const int tx = t & 15;
        const int ty = t >> 4;
        const float* wwu = ww + (size_t)u * H2d * KINd;
        const float* bwu = bw + (size_t)u * KINd;

        if (t < 64) sWbs[t] = g_sWb[u * H2d + t];
        for (int q = t; q < 1024; q += 256) {
            int r = q & 63, gq = (q >> 6) * 4;
            float4 v = *(const float4*)(g_h2 + ((size_t)(b0 + r) * 2 + u) * H2d + gq);
            h2tf[(gq + 0) * 68 + r] = v.x;
            h2tf[(gq + 1) * 68 + r] = v.y;
            h2tf[(gq + 2) * 68 + r] = v.z;
            h2tf[(gq + 3) * 68 + r] = v.w;
        }
        __syncthreads();

        ull acc2[2][4];
        float part[4] = {0.f, 0.f, 0.f, 0.f};

        for (int it = 0; it < 16; ++it) {
            int i0 = it * 64;
            __syncthreads();
            for (int q = t; q < 1024; q += 256) {
                int r = q >> 4, c = q & 15;
                *(float4*)&wws[r * 68 + c * 4] =
                    *(const float4*)(wwu + (size_t)r * KINd + i0 + c * 4);
            }
            for (int q = t; q < 1024; q += 256) {
                int r = q >> 4, c = q & 15;
                *(float4*)&xsh[r * 68 + c * 4] =
                    *(const float4*)(x + (size_t)(b0 + r) * KINd + i0 + c * 4);
            }
            if (t < 16) *(float4*)&bws[t * 4] = *(const float4*)(bwu + i0 + t * 4);
            __syncthreads();

#pragma unroll
            for (int rp = 0; rp < 2; ++rp)
#pragma unroll
                for (int j = 0; j < 4; ++j) acc2[rp][j] = 0ULL;

#pragma unroll 8
            for (int g = 0; g < 64; ++g) {
                ulonglong2 ha = *(const ulonglong2*)(h2tf + g * 68 + ty * 4);
                float4 wv = *(const float4*)&wws[g * 68 + tx * 4];
                ull w0 = pack2(wv.x, wv.x), w1p = pack2(wv.y, wv.y);
                ull w2p = pack2(wv.z, wv.z), w3p = pack2(wv.w, wv.w);
                ffma2(acc2[0][0], ha.x, w0); ffma2(acc2[0][1], ha.x, w1p);
                ffma2(acc2[0][2], ha.x, w2p); ffma2(acc2[0][3], ha.x, w3p);
                ffma2(acc2[1][0], ha.y, w0); ffma2(acc2[1][1], ha.y, w1p);
                ffma2(acc2[1][2], ha.y, w2p); ffma2(acc2[1][3], ha.y, w3p);
            }

#pragma unroll
            for (int j = 0; j < 4; ++j) {
                float bwv = bws[tx * 4 + j];
#pragma unroll
                for (int rp = 0; rp < 2; ++rp) {
                    float s0, s1;
                    unpack2(acc2[rp][j], s0, s1);
                    float p0 = sp_poly(s0 + bwv);
                    float p1 = sp_poly(s1 + bwv);
                    part[2 * rp]     += p0 * xsh[(ty * 4 + 2 * rp) * 68 + tx * 4 + j];
                    part[2 * rp + 1] += p1 * xsh[(ty * 4 + 2 * rp + 1) * 68 + tx * 4 + j];
                }
            }
        }

#pragma unroll
        for (int gg = 0; gg < 4; ++gg) {
            int g = tx * 4 + gg;
            float swv = sWbs[g];
#pragma unroll
            for (int r = 0; r < 4; ++r)
                part[r] += h2tf[g * 68 + ty * 4 + r] * swv;
        }
#pragma unroll
        for (int r = 0; r < 4; ++r)
#pragma unroll
            for (int o = 8; o > 0; o >>= 1)
                part[r] += __shfl_down_sync(0xffffffffu, part[r], o, 16);
        if (tx == 0) {
            float sbbv = g_sbb[u];
#pragma unroll
            for (int r = 0; r < 4; ++r)
                g_inner[(size_t)(b0 + ty * 4 + r) * 2 + u] = part[r] + sbbv;
        }
        __threadfence();
        __syncthreads();
        if (t == 0) g_t3done[vg3] = 1;
    } else {
        // ================= outer: waits stage2 pair + mamba group ===========
        float* i0s  = (float*)dynsm;            // [64]
        float* i1s  = i0s + 64;                 // [64]
        float* w1af = i1s + 64;                 // [128]
        float* w1bf = w1af + 128;               // [128]
        float* b1f  = w1bf + 128;               // [128]
        float* W2s  = b1f + 128;                // [32*68]
        float* g1s  = W2s + 32 * 68;            // [32*68]
        float* ob2s = g1s + 32 * 68;            // [64]
        float* owws = ob2s + 64;                // [64]
        float* owbs = owws + 64;                // [64]
        const int ob = vb - 3392;
        const int b0 = ob * 64;
        if (t == 0) {
            while (*(volatile int*)&g_t3done[2 * ob] == 0) { }
            while (*(volatile int*)&g_t3done[2 * ob + 1] == 0) { }
            while (*(volatile int*)&g_mcnt[ob] < 8) { }
            __threadfence();
        }
        __syncthreads();

        const int tx = t & 15;
        const int ty = t >> 4;

        if (t < 64) {
            float2 iv = *(const float2*)(g_inner + (size_t)(b0 + t) * 2);
            i0s[t] = iv.x;
            i1s[t] = iv.y;
        }

        float kan[4] = {0.f, 0.f, 0.f, 0.f};

#pragma unroll
        for (int v = 0; v < 2; ++v) {
            __syncthreads();
            if (t < 128) {
                w1af[t] = ow1[(v * 2 + 0) * H1d + t];
                w1bf[t] = ow1[(v * 2 + 1) * H1d + t];
                b1f[t]  = ob1[v * H1d + t];
            } else if (t < 192) {
                int j = t - 128;
                ob2s[j] = ob2[v * H2d + j];
                owws[j] = oww[v * H2d + j];
                owbs[j] = owb[v * H2d + j];
            }
            __syncthreads();

            float acc[4][4];
#pragma unroll
            for (int i = 0; i < 4; ++i)
#pragma unroll
                for (int j = 0; j < 4; ++j) acc[i][j] = 0.f;

            for (int fc = 0; fc < 4; ++fc) {
                const int f0 = fc * 32;
                __syncthreads();
                for (int q = t; q < 2048; q += 256) {
                    int f = q >> 6, b = q & 63;
                    g1s[f * 68 + b] =
                        fmaxf(fmaf(i0s[b], w1af[f0 + f],
                              fmaf(i1s[b], w1bf[f0 + f], b1f[f0 + f])), 0.f);
                }
                for (int q = t; q < 512; q += 256) {
                    int f = q >> 4, c = q & 15;
                    *(float4*)&W2s[f * 68 + c * 4] =
                        *(const float4*)(ow2 + ((size_t)v * H1d + f0 + f) * H2d + c * 4);
                }
                __syncthreads();
#pragma unroll 8
                for (int f = 0; f < 32; ++f) {
                    float4 w = *(float4*)&W2s[f * 68 + tx * 4];
                    float a0 = g1s[f * 68 + ty * 4 + 0];
                    float a1 = g1s[f * 68 + ty * 4 + 1];
                    float a2 = g1s[f * 68 + ty * 4 + 2];
                    float a3 = g1s[f * 68 + ty * 4 + 3];
                    acc[0][0] += a0 * w.x; acc[0][1] += a0 * w.y; acc[0][2] += a0 * w.z; acc[0][3] += a0 * w.w;
                    acc[1][0] += a1 * w.x; acc[1][1] += a1 * w.y; acc[1][2] += a1 * w.z; acc[1][3] += a1 * w.w;
                    acc[2][0] += a2 * w.x; acc[2][1] += a2 * w.y; acc[2][2] += a2 * w.z; acc[2][3] += a2 * w.w;
                    acc[3][0] += a3 * w.x; acc[3][1] += a3 * w.y; acc[3][2] += a3 * w.z; acc[3][3] += a3 * w.w;
                }
            }

            float swp[4], sbp[4];
#pragma unroll
            for (int i = 0; i < 4; ++i) { swp[i] = 0.f; sbp[i] = 0.f; }
#pragma unroll
            for (int j = 0; j < 4; ++j) {
                int jj = tx * 4 + j;
                float bz = ob2s[jj], wwv = owws[jj], wbv = owbs[jj];
#pragma unroll
                for (int i = 0; i < 4; ++i) {
                    float g2 = fmaxf(acc[i][j] + bz, 0.f);
                    swp[i] += g2 * wwv;
                    sbp[i] += g2 * wbv;
                }
            }
#pragma unroll
            for (int i = 0; i < 4; ++i) {
#pragma unroll
                for (int o = 8; o > 0; o >>= 1) {
                    swp[i] += __shfl_down_sync(0xffffffffu, swp[i], o, 16);
                    sbp[i] += __shfl_down_sync(0xffffffffu, sbp[i], o, 16);
                }
            }
            if (tx == 0) {
                float obwv = obw[v], obbv = obb[v];
#pragma unroll
                for (int i = 0; i < 4; ++i) {
                    int b = ty * 4 + i;
                    float wout = sp_poly(swp[i] + obwv);
                    kan[i] += wout * (i0s[b] + i1s[b]) + 2.f * (sbp[i] + obbv);
                }
            }
        }

        if (tx == 0) {
            float wkv = wk[0];
#pragma unroll
            for (int i = 0; i < 4; ++i)
                out[b0 + ty * 4 + i] += wkv * kan[i];
        }
    }
}

extern "C" void kernel_launch(void* const* d_in, const int* in_sizes, int n_in,
                              void* d_out, int out_size) {
    const float* x_kan   = (const float*)d_in[0];
    const float* x_mamba = (const float*)d_in[1];
    const float* in_w1 = (const float*)d_in[2];
    const float* in_b1 = (const float*)d_in[3];
    const float* in_w2 = (const float*)d_in[4];
    const float* in_b2 = (const float*)d_in[5];
    const float* in_ww = (const float*)d_in[6];
    const float* in_bw = (const float*)d_in[7];
    const float* in_wb = (const float*)d_in[8];
    const float* in_bb = (const float*)d_in[9];
    const float* out_w1 = (const float*)d_in[10];
    const float* out_b1 = (const float*)d_in[11];
    const float* out_w2 = (const float*)d_in[12];
    const float* out_b2 = (const float*)d_in[13];
    const float* out_ww = (const float*)d_in[14];
    const float* out_bw = (const float*)d_in[15];
    const float* out_wb = (const float*)d_in[16];
    const float* out_bb = (const float*)d_in[17];
    const float* A      = (const float*)d_in[18];
    const float* B_ssm  = (const float*)d_in[19];
    const float* C_ssm  = (const float*)d_in[20];
    const float* wk     = (const float*)d_in[21];
    const float* wm     = (const float*)d_in[22];
    float* out = (float*)d_out;

    const int MGSMEM = (256 * 34 + 256 * 36) * 4;   // 71680 (prelude max)
    cudaFuncSetAttribute(mega_kernel, cudaFuncAttributeMaxDynamicSharedMemorySize, MGSMEM);

    ksums_kernel<<<130, 32>>>(in_wb, in_bb);
    mega_kernel<<<64 + 256 + 2048 + 512 + 512 + 256, 256, MGSMEM>>>(
        x_kan, in_w1, in_b1, x_mamba, wm, A, B_ssm, C_ssm,
        in_w2, in_b2, in_ww, in_bw,
        out_w1, out_b1, out_w2, out_b2, out_ww, out_bw, out_wb, out_bb,
        wk, out);
}